// round 9
// baseline (speedup 1.0000x reference)
#include <cuda_runtime.h>
#include <cstdint>

#if defined(__CUDA_ARCH_FEAT_SM103_ALL) || \
    (defined(__CUDA_ARCH_SPECIFIC__) && (__CUDA_ARCH_SPECIFIC__ == 1030)) || \
    (defined(__CUDA_ARCH_FAMILY_SPECIFIC__) && (__CUDA_ARCH_FAMILY_SPECIFIC__ == 1030))
#define TC_PATH 1
#else
#define TC_PATH 0
#endif

#define N_NODES 16384
#define IN_DIM 256
#define HID 128
#define MAXL 128
#define NCLS 64
#define EPS 1e-5f
#define D0 4            // center window cols 0..135 (reads D0..D0+127, even bases only)
#define SA 144          // layer-0 shift -1 window (write SA+2, read SA+1)
#define SB 276          // layer-0 shift +1 window (write SB+2, read SB+3)
#define PAD 4
#define XS (MAXL + 2*PAD)
#define NSLOT 6         // TMA ring depth (16KB chunks)

// ---------------- device scratch (no allocations allowed) ----------------
__device__ float g_H[N_NODES * HID];
__device__ float g_pooled[N_NODES * HID];
__device__ float g_Wswz[10 * HID * HID];    // swizzled tf32 tiles (tensor path)
__device__ float g_Wplain[10 * HID * HID];  // plain tiles (fallback path)

// idesc kind::tf32: dtype F32(1<<4), atype TF32(2<<7), btype TF32(2<<10), N=128(16<<17), M=128(8<<24)
static constexpr uint32_t IDESC =
    (1u << 4) | (2u << 7) | (2u << 10) | (16u << 17) | (8u << 24);
// SW128 K-major smem descriptor: layout=2, version=1, SBO=64 (1024B), LBO=1 (16B)
static constexpr uint64_t DESC_BASE =
    (uint64_t(2) << 61) | (uint64_t(1) << 46) | (uint64_t(64) << 32) | (uint64_t(1) << 16);

__device__ __forceinline__ float gelu_exact(float x) {
    return 0.5f * x * (1.0f + erff(x * 0.7071067811865476f));
}
__device__ __forceinline__ float tf32r(float x) {
    uint32_t u;
    asm("cvt.rna.tf32.f32 %0, %1;" : "=r"(u) : "f"(x));
    return __uint_as_float(u);
}
__device__ __forceinline__ uint32_t smem_u32(const void* p) {
    uint32_t a;
    asm("{ .reg .u64 t; cvta.to.shared.u64 t, %1; cvt.u32.u64 %0, t; }" : "=r"(a) : "l"(p));
    return a;
}
// byte offset of (row, col) in a [128 x 128 fp32] K-major SW128 blocked tile
__device__ __forceinline__ uint32_t swz_off(int row, int col) {
    uint32_t off = ((uint32_t)(row >> 3) + (uint32_t)(col >> 5) * 16u) * 1024u
                 + (uint32_t)(row & 7) * 128u + (uint32_t)(col & 31) * 4u;
    return off ^ ((off >> 3) & 0x70u);
}

// ------------------------------------------------------------------
// Prep: weight tiles in both forms.
// tile 0: A[c][k] = ssm_in_W[k][c]; tiles 1..9: A[co][ci] = conv_w[layer][co][ci][kk]
// ------------------------------------------------------------------
__global__ void k_prep(const float* __restrict__ ssmW, const float* __restrict__ convW) {
    int e = blockIdx.x * blockDim.x + threadIdx.x;
    if (e >= 10 * HID * HID) return;
    int tile = e >> 14;
    int r = (e >> 7) & 127;
    int k = e & 127;
    float v;
    if (tile == 0) {
        v = ssmW[k * HID + r];
    } else {
        int t = tile - 1, layer = t / 3, kk = t % 3;
        v = convW[((layer * HID + r) * HID + k) * 3 + kk];
    }
    g_Wplain[tile * (HID * HID) + k * HID + r] = v;
    *(float*)((char*)(g_Wswz + tile * (HID * HID)) + swz_off(r, k)) = tf32r(v);
}

// ------------------------------------------------------------------
// Local encoder, 8 nodes per block
// ------------------------------------------------------------------
__global__ __launch_bounds__(128) void k_local8(
    const float* __restrict__ feat, const float* __restrict__ W,
    const float* __restrict__ b, const float* __restrict__ lnw,
    const float* __restrict__ lnb)
{
    __shared__ float xs[8 * IN_DIM];
    __shared__ float reds[32], redq[32];
    int base = blockIdx.x * 8;
    int c = threadIdx.x;
    for (int e = c; e < 8 * IN_DIM; e += 128)
        xs[e] = feat[base * IN_DIM + e];
    __syncthreads();

    float acc[8];
    float bb = b[c];
    #pragma unroll
    for (int nb = 0; nb < 8; ++nb) acc[nb] = bb;
    for (int i = 0; i < IN_DIM; ++i) {
        float wv = W[i * HID + c];
        #pragma unroll
        for (int nb = 0; nb < 8; ++nb) acc[nb] += xs[nb * IN_DIM + i] * wv;
    }
    int warp = c >> 5, lane = c & 31;
    float v[8];
    #pragma unroll
    for (int nb = 0; nb < 8; ++nb) {
        v[nb] = gelu_exact(acc[nb]);
        float s = v[nb], q = v[nb] * v[nb];
        #pragma unroll
        for (int off = 16; off; off >>= 1) {
            s += __shfl_xor_sync(0xffffffffu, s, off);
            q += __shfl_xor_sync(0xffffffffu, q, off);
        }
        if (lane == 0) { reds[warp * 8 + nb] = s; redq[warp * 8 + nb] = q; }
    }
    __syncthreads();
    #pragma unroll
    for (int nb = 0; nb < 8; ++nb) {
        float s = reds[nb] + reds[8 + nb] + reds[16 + nb] + reds[24 + nb];
        float q = redq[nb] + redq[8 + nb] + redq[16 + nb] + redq[24 + nb];
        float m = s * (1.f / HID);
        float inv = rsqrtf(q * (1.f / HID) - m * m + EPS);
        g_H[(base + nb) * HID + c] = (v[nb] - m) * inv * lnw[c] + lnb[c];
    }
}

// ================= tensor-path helpers (guarded) =================
#if TC_PATH
#define MBAR_INIT(a, cnt) \
    asm volatile("mbarrier.init.shared.b64 [%0], %1;" :: "r"(a), "r"((uint32_t)(cnt)) : "memory")
#define MBAR_EXPECT(a, bytes) \
    asm volatile("mbarrier.arrive.expect_tx.shared.b64 _, [%0], %1;" :: "r"(a), "r"((uint32_t)(bytes)) : "memory")

__device__ __forceinline__ void mbar_wait(uint32_t mbar, int parity) {
    asm volatile(
        "{\n\t.reg .pred P1;\n\t"
        "WL_%=:\n\t"
        "mbarrier.try_wait.parity.acquire.cta.shared::cta.b64 P1, [%0], %1, 0x989680;\n\t"
        "@P1 bra.uni WD_%=;\n\t"
        "bra.uni WL_%=;\n\t"
        "WD_%=:\n\t}"
        :: "r"(mbar), "r"((uint32_t)parity) : "memory");
}
__device__ __forceinline__ void bulk_g2s(uint32_t dst, const void* src, uint32_t bytes, uint32_t mbar) {
    asm volatile(
        "cp.async.bulk.shared::cluster.global.mbarrier::complete_tx::bytes [%0], [%1], %2, [%3];"
        :: "r"(dst), "l"(src), "r"(bytes), "r"(mbar) : "memory");
}

#define TC_ALLOC(sa, n) \
    asm volatile("tcgen05.alloc.cta_group::1.sync.aligned.shared::cta.b32 [%0], %1;" :: "r"(sa), "r"((uint32_t)(n)) : "memory")
#define TC_RELINQ() \
    asm volatile("tcgen05.relinquish_alloc_permit.cta_group::1.sync.aligned;")
#define TC_DEALLOC(t, n) \
    asm volatile("tcgen05.dealloc.cta_group::1.sync.aligned.b32 %0, %1;" :: "r"(t), "r"((uint32_t)(n)))
#define TC_COMMIT(mb) \
    asm volatile("tcgen05.commit.cta_group::1.mbarrier::arrive::one.shared::cluster.b64 [%0];" :: "r"(mb) : "memory")
#define TC_FENCE_BEFORE() asm volatile("tcgen05.fence::before_thread_sync;" ::: "memory")
#define TC_FENCE_AFTER()  asm volatile("tcgen05.fence::after_thread_sync;" ::: "memory")
#define TC_WAIT_LD() asm volatile("tcgen05.wait::ld.sync.aligned;" ::: "memory")
#define TC_WAIT_ST() asm volatile("tcgen05.wait::st.sync.aligned;" ::: "memory")
#define FENCE_PROXY() asm volatile("fence.proxy.async.shared::cta;" ::: "memory")

#define TCLD32(r, adr) \
    asm volatile( \
        "tcgen05.ld.sync.aligned.32x32b.x32.b32 " \
        "{%0, %1, %2, %3, %4, %5, %6, %7, %8, %9, %10, %11, %12, %13, %14, %15, " \
        " %16, %17, %18, %19, %20, %21, %22, %23, %24, %25, %26, %27, %28, %29, %30, %31}, [%32];" \
        : "=r"((r)[0]),  "=r"((r)[1]),  "=r"((r)[2]),  "=r"((r)[3]), \
          "=r"((r)[4]),  "=r"((r)[5]),  "=r"((r)[6]),  "=r"((r)[7]), \
          "=r"((r)[8]),  "=r"((r)[9]),  "=r"((r)[10]), "=r"((r)[11]), \
          "=r"((r)[12]), "=r"((r)[13]), "=r"((r)[14]), "=r"((r)[15]), \
          "=r"((r)[16]), "=r"((r)[17]), "=r"((r)[18]), "=r"((r)[19]), \
          "=r"((r)[20]), "=r"((r)[21]), "=r"((r)[22]), "=r"((r)[23]), \
          "=r"((r)[24]), "=r"((r)[25]), "=r"((r)[26]), "=r"((r)[27]), \
          "=r"((r)[28]), "=r"((r)[29]), "=r"((r)[30]), "=r"((r)[31]) \
        : "r"(adr))

#define TCST2(adr, r0, r1) \
    asm volatile("tcgen05.st.sync.aligned.32x32b.x2.b32 [%0], {%1, %2};" \
                 :: "r"(adr), "r"(r0), "r"(r1) : "memory")

__device__ __forceinline__ void mma_tf32(uint32_t d, uint64_t a, uint64_t b, uint32_t en) {
    asm volatile(
        "{\n\t.reg .pred p;\n\tsetp.ne.u32 p, %4, 0;\n\t"
        "tcgen05.mma.cta_group::1.kind::tf32 [%0], %1, %2, %3, {%5, %5, %5, %5}, p;\n\t}"
        :: "r"(d), "l"(a), "l"(b), "r"(IDESC), "r"(en), "r"(0u) : "memory");
}
#endif  // TC_PATH

// ================= fallback fp32 microkernel (compiled always; dead on sm_103a) =================
template<int SHIFT>
__device__ __forceinline__ void gemm_tap(float C[8][8], const float* __restrict__ Wt,
                                         const float* __restrict__ B, int m0, int n0)
{
    const float* brow = B + PAD + n0 + SHIFT;
    const float* wrow = Wt + m0;
    #pragma unroll 2
    for (int k = 0; k < HID; ++k) {
        float a[8], bb[8];
        float4 a0 = *(const float4*)(wrow);
        float4 a1 = *(const float4*)(wrow + 4);
        a[0]=a0.x; a[1]=a0.y; a[2]=a0.z; a[3]=a0.w;
        a[4]=a1.x; a[5]=a1.y; a[6]=a1.z; a[7]=a1.w;
        #pragma unroll
        for (int j = 0; j < 8; ++j) bb[j] = brow[j];
        #pragma unroll
        for (int i = 0; i < 8; ++i)
            #pragma unroll
            for (int j = 0; j < 8; ++j)
                C[i][j] += a[i] * bb[j];
        wrow += HID;
        brow += XS;
    }
}

// ------------------------------------------------------------------
// Main kernel. smem (floats, 1KB-aligned base):
//   Bt@0 (16384) | A ring @16384 (6*4096) | Par@40960 (1280)
//   | RedS@42240 (256) | RedQ@42496 (256) | Svec@42752 (128) | misc bytes @171520
// ------------------------------------------------------------------
#define SMF_ARING 16384
#define SMF_PAR   40960
#define SMF_REDS  42240
#define SMF_REDQ  42496
#define SMF_SVEC  42752
#define SMB_MISC  171520
#define SMEM_TOTAL 172736

__global__ __launch_bounds__(256, 1) void k_main(
    const int* __restrict__ nidx, const int* __restrict__ nlen,
    const float* __restrict__ ssmB, const float* __restrict__ convB,
    const float* __restrict__ lnW, const float* __restrict__ lnB,
    const float* __restrict__ outW, const float* __restrict__ outB)
{
    extern __shared__ float smf[];
    const int n = blockIdx.x;
    const int tid = threadIdx.x;
    const int len = nlen[n];

#if TC_PATH
    uint32_t raw = smem_u32(smf);
    uint32_t sbase = (raw + 1023u) & ~1023u;
    float* bas = smf + (sbase - raw) / 4;

    float* Bt   = bas;
    float* Par  = bas + SMF_PAR;
    float* RedS = bas + SMF_REDS;
    float* RedQ = bas + SMF_REDQ;
    float* Svec = bas + SMF_SVEC;
    uint32_t Baddr = sbase;
    uint32_t miscb = sbase + SMB_MISC;        // tmem ptr @+0
    // mbarriers: tma[6] @ +8.. , mma[6] @ +56.., grp @ +104
    uint32_t mb_tma0 = miscb + 8;
    uint32_t mb_mma0 = miscb + 56;
    uint32_t mb_grp  = miscb + 104;

    const int w = tid >> 5, lane = tid & 31;
    const int h = w >> 2;                  // column half
    const int c = (w & 3) * 32 + lane;     // channel (TMEM row) owned
    const uint32_t woff = (uint32_t)(w & 3) << 21;

    if (tid == 0) {
        #pragma unroll
        for (int s = 0; s < NSLOT; ++s) {
            MBAR_INIT(mb_tma0 + 8 * s, 1);
            MBAR_INIT(mb_mma0 + 8 * s, 1);
        }
        MBAR_INIT(mb_grp, 1);
    }
    for (int e = tid; e < 128; e += 256) Par[e] = ssmB[e];
    for (int e = tid; e < 384; e += 256) Par[128 + e] = convB[e];
    for (int e = tid; e < 384; e += 256) Par[512 + e] = lnW[e];
    for (int e = tid; e < 384; e += 256) Par[896 + e] = lnB[e];
    if (w == 0) TC_ALLOC(miscb, 512);
    __syncthreads();
    uint32_t tmem;
    asm("ld.shared.b32 %0, [%1];" : "=r"(tmem) : "r"(miscb));
    if (w == 0) TC_RELINQ();

    // chunk consumption order: 40 chunks = 10 taps x 4 K-chunks
    // tap t uses tile TSEQ[t]; chunk q is (tap q>>2, sub q&3); gmem src = tile*16384 + sub*4096 floats
    // preload chunks 0..5 into ring slots 0..5
    if (tid == 0) {
        #pragma unroll
        for (int s = 0; s < NSLOT; ++s) {
            int tap = s >> 2, sub = s & 3;
            int tile = (tap == 0) ? 0 : 1;   // chunks 0..3 -> tile 0; 4,5 -> tile 1 (TSEQ[1]=1)
            MBAR_EXPECT(mb_tma0 + 8 * s, 16384);
            bulk_g2s(sbase + (uint32_t)(SMF_ARING + s * 4096) * 4u,
                     g_Wswz + tile * 16384 + sub * 4096, 16384, mb_tma0 + 8 * s);
        }
    }

    // gather masked neighbor rows: B[l][k] = H[idx[l]][k]
    const int* idxrow = nidx + n * MAXL;
    for (int e = tid; e < MAXL * HID; e += 256) {
        int l = e >> 7, k = e & 127;
        float v = 0.f;
        if (l < len) v = g_H[idxrow[l] * HID + k];
        *(float*)((char*)Bt + swz_off(l, k)) = tf32r(v);
    }

    // zero margin columns of side windows: SA..SA+1 and SB+130..SB+131 (all 128 rows)
    if (h == 0) {
        uint32_t tb = tmem + woff;
        TCST2(tb + SA, 0u, 0u);
        TCST2(tb + SB + 130, 0u, 0u);
        TC_WAIT_ST();
        TC_FENCE_BEFORE();
    }

    int q = 0;
    uint32_t va[32], vb[32];

    for (int stage = 0; stage < 4; ++stage) {
        __syncthreads();   // B tile ready; TMEM stores visible

        if (tid == 0) {
            // per-tap: weight tile, D write base, overwrite-on-first-chunk flag
            const int TSEQ[10] = {0, 1, 2, 3, 5, 4, 6, 8, 7, 9};
            const int DBASE[10]= {D0, SA + 2, D0, SB + 2, D0, D0 + 2, D0 - 2, D0, D0 + 4, D0 - 4};
            const int INITT[10]= {1, 1, 1, 1, 1, 0, 0, 1, 0, 0};
            FENCE_PROXY();
            TC_FENCE_AFTER();
            uint64_t bd0 = DESC_BASE | ((uint64_t)((Baddr >> 4) & 0x3FFFu));
            int qe = 4 + 12 * stage;
            for (; q < qe; ++q) {
                int tap = q >> 2, sub = q & 3;
                int slot = q % NSLOT, ph = (q / NSLOT) & 1;
                mbar_wait(mb_tma0 + 8 * slot, ph);
                uint32_t aaddr = sbase + (uint32_t)(SMF_ARING + slot * 4096) * 4u;
                uint64_t ad = DESC_BASE | ((uint64_t)((aaddr >> 4) & 0x3FFFu));
                uint64_t bd = bd0 + (uint64_t)(sub * 1024);
                uint32_t dadr = tmem + (uint32_t)DBASE[tap];
                #pragma unroll
                for (int ks = 0; ks < 4; ++ks) {
                    uint32_t en = (ks == 0 && sub == 0 && INITT[tap]) ? 0u : 1u;
                    mma_tf32(dadr, ad + ks * 2, bd + ks * 2, en);
                }
                TC_COMMIT(mb_mma0 + 8 * slot);
                // non-blocking refill: chunk cR = q-2 finished ~2 chunks ago
                int cR = q - 2;
                if (cR >= 0 && cR + NSLOT < 40) {
                    int rs = cR % NSLOT, rph = (cR / NSLOT) & 1;
                    mbar_wait(mb_mma0 + 8 * rs, rph);
                    int cN = cR + NSLOT;
                    const float* src = g_Wswz + TSEQ[cN >> 2] * 16384 + (cN & 3) * 4096;
                    MBAR_EXPECT(mb_tma0 + 8 * rs, 16384);
                    bulk_g2s(sbase + (uint32_t)(SMF_ARING + rs * 4096) * 4u, src, 16384,
                             mb_tma0 + 8 * rs);
                }
            }
            TC_COMMIT(mb_grp);   // fires when ALL prior MMAs of this CTA complete
        }
        mbar_wait(mb_grp, stage & 1);
        TC_FENCE_AFTER();

        // ---- epilogue: read D window (plus side windows at stage 1) ----
        TCLD32(va, tmem + woff + (uint32_t)(D0 + 64 * h));
        TCLD32(vb, tmem + woff + (uint32_t)(D0 + 64 * h + 32));
        if (stage == 1) {
            uint32_t ta[32], tb2[32];
            TCLD32(ta,  tmem + woff + (uint32_t)(SA + 1 + 64 * h));
            TCLD32(tb2, tmem + woff + (uint32_t)(SA + 1 + 64 * h + 32));
            TC_WAIT_LD();
            #pragma unroll
            for (int j = 0; j < 32; ++j) {
                va[j] = __float_as_uint(__uint_as_float(va[j]) + __uint_as_float(ta[j]));
                vb[j] = __float_as_uint(__uint_as_float(vb[j]) + __uint_as_float(tb2[j]));
            }
            TCLD32(ta,  tmem + woff + (uint32_t)(SB + 3 + 64 * h));
            TCLD32(tb2, tmem + woff + (uint32_t)(SB + 3 + 64 * h + 32));
            TC_WAIT_LD();
            #pragma unroll
            for (int j = 0; j < 32; ++j) {
                va[j] = __float_as_uint(__uint_as_float(va[j]) + __uint_as_float(ta[j]));
                vb[j] = __float_as_uint(__uint_as_float(vb[j]) + __uint_as_float(tb2[j]));
            }
        } else {
            TC_WAIT_LD();
        }

        if (stage == 0) {
            float bv = Par[c];
            #pragma unroll
            for (int j = 0; j < 32; ++j) {
                int l = 64 * h + j;
                *(float*)((char*)Bt + swz_off(l, c)) = tf32r(__uint_as_float(va[j]) + bv);
            }
            #pragma unroll
            for (int j = 0; j < 32; ++j) {
                int l = 64 * h + 32 + j;
                *(float*)((char*)Bt + swz_off(l, c)) = tf32r(__uint_as_float(vb[j]) + bv);
            }
        } else {
            int layer = stage - 1;
            float bv = Par[128 + layer * 128 + c];
            float s = 0.f, q2 = 0.f;
            #pragma unroll
            for (int j = 0; j < 32; ++j) {
                float z = gelu_exact(__uint_as_float(va[j]) + bv);
                va[j] = __float_as_uint(z); s += z; q2 += z * z;
            }
            #pragma unroll
            for (int j = 0; j < 32; ++j) {
                float z = gelu_exact(__uint_as_float(vb[j]) + bv);
                vb[j] = __float_as_uint(z); s += z; q2 += z * z;
            }
            RedS[h * 128 + c] = s;
            RedQ[h * 128 + c] = q2;
            __syncthreads();
            float st = s + RedS[(h ^ 1) * 128 + c];
            float qt = q2 + RedQ[(h ^ 1) * 128 + c];
            float m   = st * (1.f / 128.f);
            float inv = rsqrtf(qt * (1.f / 128.f) - m * m + EPS);
            const float* lw = Par + 512 + layer * 128;
            const float* lb = Par + 896 + layer * 128;
            if (stage < 3) {
                #pragma unroll
                for (int j = 0; j < 32; ++j) {
                    int l = 64 * h + j;
                    float o = (__uint_as_float(va[j]) - m) * inv * lw[l] + lb[l];
                    *(float*)((char*)Bt + swz_off(l, c)) = tf32r(o);
                }
                #pragma unroll
                for (int j = 0; j < 32; ++j) {
                    int l = 64 * h + 32 + j;
                    float o = (__uint_as_float(vb[j]) - m) * inv * lw[l] + lb[l];
                    *(float*)((char*)Bt + swz_off(l, c)) = tf32r(o);
                }
            } else {
                float ms = 0.f;
                #pragma unroll
                for (int j = 0; j < 32; ++j) {
                    int l = 64 * h + j;
                    float o = (__uint_as_float(va[j]) - m) * inv * lw[l] + lb[l];
                    if (l < len) ms += o;
                }
                #pragma unroll
                for (int j = 0; j < 32; ++j) {
                    int l = 64 * h + 32 + j;
                    float o = (__uint_as_float(vb[j]) - m) * inv * lw[l] + lb[l];
                    if (l < len) ms += o;
                }
                __syncthreads();
                RedS[h * 128 + c] = ms;
                __syncthreads();
                if (h == 0) Svec[c] = RedS[c] + RedS[128 + c];
                __syncthreads();
                if (tid < 128) {
                    float acc = 0.f;
                    #pragma unroll 8
                    for (int cc = 0; cc < 128; ++cc)
                        acc += Svec[cc] * outW[cc * 128 + tid];
                    float cnt = (float)len, denom = fmaxf(cnt, 1.f);
                    g_pooled[n * 128 + tid] = (acc + cnt * outB[tid]) / denom;
                }
            }
        }
    }
    __syncthreads();
    if (w == 0) TC_DEALLOC(tmem, 512);

#else  // ===================== fp32 fallback body (dead on sm_103a device) =====================
    float* Xa   = smf;
    float* Xb   = smf + HID * XS;
    float* Wt   = smf + 2 * HID * XS;
    float* svec = Wt + HID * HID;

    const int tx = tid & 15, ty = tid >> 4;
    const int m0 = ty * 8, n0 = tx * 8;

    for (int e = tid; e < HID * 8; e += 256) {
        int r = e >> 3, p = e & 7;
        int col = (p < PAD) ? p : (XS - 8 + p);
        Xa[r * XS + col] = 0.f;
        Xb[r * XS + col] = 0.f;
    }
    const int* idxrow = nidx + n * MAXL;
    for (int e = tid; e < MAXL * HID; e += 256) {
        int l = e >> 7, k = e & (HID - 1);
        float v = 0.f;
        if (l < len) v = g_H[idxrow[l] * HID + k];
        Xa[k * XS + PAD + l] = v;
    }
    for (int e = tid; e < HID * HID; e += 256) Wt[e] = g_Wplain[e];
    __syncthreads();

    float C[8][8];
    #pragma unroll
    for (int i = 0; i < 8; ++i)
        #pragma unroll
        for (int j = 0; j < 8; ++j) C[i][j] = 0.f;
    gemm_tap<0>(C, Wt, Xa, m0, n0);
    #pragma unroll
    for (int i = 0; i < 8; ++i) {
        float bv = ssmB[m0 + i];
        #pragma unroll
        for (int j = 0; j < 8; ++j)
            Xb[(m0 + i) * XS + PAD + n0 + j] = C[i][j] + bv;
    }
    __syncthreads();

    float* src = Xb;
    float* dst = Xa;
    for (int layer = 0; layer < 3; ++layer) {
        const int d = 1 << layer;
        #pragma unroll
        for (int i = 0; i < 8; ++i)
            #pragma unroll
            for (int j = 0; j < 8; ++j) C[i][j] = 0.f;
        for (int kk = 0; kk < 3; ++kk) {
            const float* wsrc = g_Wplain + (1 + layer * 3 + kk) * (HID * HID);
            for (int e = tid; e < HID * HID; e += 256) Wt[e] = wsrc[e];
            __syncthreads();
            int shift = (kk - 1) * d;
            switch (shift) {
                case -4: gemm_tap<-4>(C, Wt, src, m0, n0); break;
                case -2: gemm_tap<-2>(C, Wt, src, m0, n0); break;
                case -1: gemm_tap<-1>(C, Wt, src, m0, n0); break;
                case  0: gemm_tap< 0>(C, Wt, src, m0, n0); break;
                case  1: gemm_tap< 1>(C, Wt, src, m0, n0); break;
                case  2: gemm_tap< 2>(C, Wt, src, m0, n0); break;
                default: gemm_tap< 4>(C, Wt, src, m0, n0); break;
            }
            __syncthreads();
        }
        float rs[8], rq[8];
        #pragma unroll
        for (int i = 0; i < 8; ++i) {
            float bv = convB[layer * HID + m0 + i];
            rs[i] = 0.f; rq[i] = 0.f;
            #pragma unroll
            for (int j = 0; j < 8; ++j) {
                float z = gelu_exact(C[i][j] + bv);
                C[i][j] = z; rs[i] += z; rq[i] += z * z;
            }
        }
        #pragma unroll
        for (int i = 0; i < 8; ++i) {
            #pragma unroll
            for (int off = 8; off; off >>= 1) {
                rs[i] += __shfl_xor_sync(0xffffffffu, rs[i], off);
                rq[i] += __shfl_xor_sync(0xffffffffu, rq[i], off);
            }
        }
        float lw[8], lb[8];
        #pragma unroll
        for (int j = 0; j < 8; ++j) {
            lw[j] = lnW[layer * HID + n0 + j];
            lb[j] = lnB[layer * HID + n0 + j];
        }
        if (layer < 2) {
            #pragma unroll
            for (int i = 0; i < 8; ++i) {
                float m   = rs[i] * (1.f / MAXL);
                float inv = rsqrtf(rq[i] * (1.f / MAXL) - m * m + EPS);
                #pragma unroll
                for (int j = 0; j < 8; ++j)
                    dst[(m0 + i) * XS + PAD + n0 + j] = (C[i][j] - m) * inv * lw[j] + lb[j];
            }
            float* t = src; src = dst; dst = t;
            __syncthreads();
        } else {
            float ms[8];
            #pragma unroll
            for (int i = 0; i < 8; ++i) {
                float m   = rs[i] * (1.f / MAXL);
                float inv = rsqrtf(rq[i] * (1.f / MAXL) - m * m + EPS);
                ms[i] = 0.f;
                #pragma unroll
                for (int j = 0; j < 8; ++j) {
                    float o = (C[i][j] - m) * inv * lw[j] + lb[j];
                    if (n0 + j < len) ms[i] += o;
                }
            }
            #pragma unroll
            for (int i = 0; i < 8; ++i) {
                #pragma unroll
                for (int off = 8; off; off >>= 1)
                    ms[i] += __shfl_xor_sync(0xffffffffu, ms[i], off);
            }
            if (tx == 0) {
                #pragma unroll
                for (int i = 0; i < 8; ++i) svec[m0 + i] = ms[i];
            }
        }
    }
    __syncthreads();
    if (tid < HID) {
        float acc = 0.f;
        #pragma unroll 8
        for (int cc = 0; cc < HID; ++cc)
            acc += svec[cc] * outW[cc * HID + tid];
        float cnt   = (float)len;
        float denom = fmaxf(cnt, 1.f);
        g_pooled[n * HID + tid] = (acc + cnt * outB[tid]) / denom;
    }
#endif
}

// ------------------------------------------------------------------
// Classifier head
// ------------------------------------------------------------------
__global__ __launch_bounds__(64) void k_cls(
    const float* __restrict__ W1, const float* __restrict__ b1,
    const float* __restrict__ W2, const float* __restrict__ b2,
    float* __restrict__ out)
{
    __shared__ float p[HID];
    __shared__ float g[64];
    int n = blockIdx.x;
    int j = threadIdx.x;
    p[j]      = g_pooled[n * HID + j];
    p[j + 64] = g_pooled[n * HID + j + 64];
    __syncthreads();
    float acc = b1[j];
    #pragma unroll 8
    for (int cc = 0; cc < HID; ++cc)
        acc += p[cc] * W1[cc * 64 + j];
    g[j] = gelu_exact(acc);
    __syncthreads();
    float acc2 = b2[j];
    #pragma unroll 8
    for (int t = 0; t < 64; ++t)
        acc2 += g[t] * W2[t * 64 + j];
    out[n * NCLS + j] = acc2;
}

// ------------------------------------------------------------------
extern "C" void kernel_launch(void* const* d_in, const int* in_sizes, int n_in,
                              void* d_out, int out_size)
{
    (void)in_sizes; (void)n_in; (void)out_size;
    const float* node_feat  = (const float*)d_in[0];
    const int*   nidx       = (const int*)  d_in[1];
    const int*   nlen       = (const int*)  d_in[2];
    const float* local_W    = (const float*)d_in[3];
    const float* local_b    = (const float*)d_in[4];
    const float* local_ln_w = (const float*)d_in[5];
    const float* local_ln_b = (const float*)d_in[6];
    const float* ssm_in_W   = (const float*)d_in[7];
    const float* ssm_in_b   = (const float*)d_in[8];
    const float* conv_w     = (const float*)d_in[9];
    const float* conv_b     = (const float*)d_in[10];
    const float* ln_w       = (const float*)d_in[11];
    const float* ln_b       = (const float*)d_in[12];
    const float* out_W      = (const float*)d_in[13];
    const float* out_b      = (const float*)d_in[14];
    const float* cls_W1     = (const float*)d_in[15];
    const float* cls_b1     = (const float*)d_in[16];
    const float* cls_W2     = (const float*)d_in[17];
    const float* cls_b2     = (const float*)d_in[18];
    float* out = (float*)d_out;

    cudaFuncSetAttribute(k_main, cudaFuncAttributeMaxDynamicSharedMemorySize, SMEM_TOTAL);

    k_prep<<<(10 * HID * HID + 255) / 256, 256>>>(ssm_in_W, conv_w);
    k_local8<<<N_NODES / 8, 128>>>(node_feat, local_W, local_b, local_ln_w, local_ln_b);
    k_main<<<N_NODES, 256, SMEM_TOTAL>>>(nidx, nlen, ssm_in_b, conv_b, ln_w, ln_b, out_W, out_b);
    k_cls<<<N_NODES, 64>>>(cls_W1, cls_b1, cls_W2, cls_b2, out);
}

// round 10
// speedup vs baseline: 1.7814x; 1.7814x over previous
#include <cuda_runtime.h>
#include <cstdint>

#if defined(__CUDA_ARCH_FEAT_SM103_ALL) || \
    (defined(__CUDA_ARCH_SPECIFIC__) && (__CUDA_ARCH_SPECIFIC__ == 1030)) || \
    (defined(__CUDA_ARCH_FAMILY_SPECIFIC__) && (__CUDA_ARCH_FAMILY_SPECIFIC__ == 1030))
#define TC_PATH 1
#else
#define TC_PATH 0
#endif

#define N_NODES 16384
#define IN_DIM 256
#define HID 128
#define MAXL 128
#define NCLS 64
#define EPS 1e-5f
#define D0 4            // center window cols 0..135 (reads D0..D0+127, even bases only)
#define SA 144          // layer-0 shift -1 window (write SA+2, read SA+1)
#define SB 276          // layer-0 shift +1 window (write SB+2, read SB+3)
#define PAD 4
#define XS (MAXL + 2*PAD)
#define NSLOT 4         // TMA ring depth (32KB chunks)
#define NCHUNK 20       // 10 taps x 2 half-tiles

// ---------------- device scratch (no allocations allowed) ----------------
__device__ float g_H[N_NODES * HID];
__device__ float g_pooled[N_NODES * HID];
__device__ float g_Wswz[10 * HID * HID];    // swizzled tf32 tiles (tensor path)
__device__ float g_Wplain[10 * HID * HID];  // plain tiles (fallback path)

// idesc kind::tf32: dtype F32(1<<4), atype TF32(2<<7), btype TF32(2<<10), N=128(16<<17), M=128(8<<24)
static constexpr uint32_t IDESC =
    (1u << 4) | (2u << 7) | (2u << 10) | (16u << 17) | (8u << 24);
// SW128 K-major smem descriptor: layout=2, version=1, SBO=64 (1024B), LBO=1 (16B)
static constexpr uint64_t DESC_BASE =
    (uint64_t(2) << 61) | (uint64_t(1) << 46) | (uint64_t(64) << 32) | (uint64_t(1) << 16);

__device__ __forceinline__ float gelu_exact(float x) {
    return 0.5f * x * (1.0f + erff(x * 0.7071067811865476f));
}
__device__ __forceinline__ float tf32r(float x) {
    uint32_t u;
    asm("cvt.rna.tf32.f32 %0, %1;" : "=r"(u) : "f"(x));
    return __uint_as_float(u);
}
__device__ __forceinline__ uint32_t smem_u32(const void* p) {
    uint32_t a;
    asm("{ .reg .u64 t; cvta.to.shared.u64 t, %1; cvt.u32.u64 %0, t; }" : "=r"(a) : "l"(p));
    return a;
}
// byte offset of (row, col) in a [128 x 128 fp32] K-major SW128 blocked tile
__device__ __forceinline__ uint32_t swz_off(int row, int col) {
    uint32_t off = ((uint32_t)(row >> 3) + (uint32_t)(col >> 5) * 16u) * 1024u
                 + (uint32_t)(row & 7) * 128u + (uint32_t)(col & 31) * 4u;
    return off ^ ((off >> 3) & 0x70u);
}

// ------------------------------------------------------------------
// Prep: weight tiles in both forms.
// tile 0: A[c][k] = ssm_in_W[k][c]; tiles 1..9: A[co][ci] = conv_w[layer][co][ci][kk]
// ------------------------------------------------------------------
__global__ void k_prep(const float* __restrict__ ssmW, const float* __restrict__ convW) {
    int e = blockIdx.x * blockDim.x + threadIdx.x;
    if (e >= 10 * HID * HID) return;
    int tile = e >> 14;
    int r = (e >> 7) & 127;
    int k = e & 127;
    float v;
    if (tile == 0) {
        v = ssmW[k * HID + r];
    } else {
        int t = tile - 1, layer = t / 3, kk = t % 3;
        v = convW[((layer * HID + r) * HID + k) * 3 + kk];
    }
    g_Wplain[tile * (HID * HID) + k * HID + r] = v;
    *(float*)((char*)(g_Wswz + tile * (HID * HID)) + swz_off(r, k)) = tf32r(v);
}

// ------------------------------------------------------------------
// Local encoder, 8 nodes per block
// ------------------------------------------------------------------
__global__ __launch_bounds__(128) void k_local8(
    const float* __restrict__ feat, const float* __restrict__ W,
    const float* __restrict__ b, const float* __restrict__ lnw,
    const float* __restrict__ lnb)
{
    __shared__ float xs[8 * IN_DIM];
    __shared__ float reds[32], redq[32];
    int base = blockIdx.x * 8;
    int c = threadIdx.x;
    for (int e = c; e < 8 * IN_DIM; e += 128)
        xs[e] = feat[base * IN_DIM + e];
    __syncthreads();

    float acc[8];
    float bb = b[c];
    #pragma unroll
    for (int nb = 0; nb < 8; ++nb) acc[nb] = bb;
    for (int i = 0; i < IN_DIM; ++i) {
        float wv = W[i * HID + c];
        #pragma unroll
        for (int nb = 0; nb < 8; ++nb) acc[nb] += xs[nb * IN_DIM + i] * wv;
    }
    int warp = c >> 5, lane = c & 31;
    float v[8];
    #pragma unroll
    for (int nb = 0; nb < 8; ++nb) {
        v[nb] = gelu_exact(acc[nb]);
        float s = v[nb], q = v[nb] * v[nb];
        #pragma unroll
        for (int off = 16; off; off >>= 1) {
            s += __shfl_xor_sync(0xffffffffu, s, off);
            q += __shfl_xor_sync(0xffffffffu, q, off);
        }
        if (lane == 0) { reds[warp * 8 + nb] = s; redq[warp * 8 + nb] = q; }
    }
    __syncthreads();
    #pragma unroll
    for (int nb = 0; nb < 8; ++nb) {
        float s = reds[nb] + reds[8 + nb] + reds[16 + nb] + reds[24 + nb];
        float q = redq[nb] + redq[8 + nb] + redq[16 + nb] + redq[24 + nb];
        float m = s * (1.f / HID);
        float inv = rsqrtf(q * (1.f / HID) - m * m + EPS);
        g_H[(base + nb) * HID + c] = (v[nb] - m) * inv * lnw[c] + lnb[c];
    }
}

// ================= tensor-path helpers (guarded) =================
#if TC_PATH
#define MBAR_INIT(a, cnt) \
    asm volatile("mbarrier.init.shared.b64 [%0], %1;" :: "r"(a), "r"((uint32_t)(cnt)) : "memory")
#define MBAR_EXPECT(a, bytes) \
    asm volatile("mbarrier.arrive.expect_tx.shared.b64 _, [%0], %1;" :: "r"(a), "r"((uint32_t)(bytes)) : "memory")

__device__ __forceinline__ void mbar_wait(uint32_t mbar, int parity) {
    asm volatile(
        "{\n\t.reg .pred P1;\n\t"
        "WL_%=:\n\t"
        "mbarrier.try_wait.parity.acquire.cta.shared::cta.b64 P1, [%0], %1, 0x989680;\n\t"
        "@P1 bra.uni WD_%=;\n\t"
        "bra.uni WL_%=;\n\t"
        "WD_%=:\n\t}"
        :: "r"(mbar), "r"((uint32_t)parity) : "memory");
}
__device__ __forceinline__ void bulk_g2s(uint32_t dst, const void* src, uint32_t bytes, uint32_t mbar) {
    asm volatile(
        "cp.async.bulk.shared::cluster.global.mbarrier::complete_tx::bytes [%0], [%1], %2, [%3];"
        :: "r"(dst), "l"(src), "r"(bytes), "r"(mbar) : "memory");
}

#define TC_ALLOC(sa, n) \
    asm volatile("tcgen05.alloc.cta_group::1.sync.aligned.shared::cta.b32 [%0], %1;" :: "r"(sa), "r"((uint32_t)(n)) : "memory")
#define TC_RELINQ() \
    asm volatile("tcgen05.relinquish_alloc_permit.cta_group::1.sync.aligned;")
#define TC_DEALLOC(t, n) \
    asm volatile("tcgen05.dealloc.cta_group::1.sync.aligned.b32 %0, %1;" :: "r"(t), "r"((uint32_t)(n)))
#define TC_COMMIT(mb) \
    asm volatile("tcgen05.commit.cta_group::1.mbarrier::arrive::one.shared::cluster.b64 [%0];" :: "r"(mb) : "memory")
#define TC_FENCE_BEFORE() asm volatile("tcgen05.fence::before_thread_sync;" ::: "memory")
#define TC_FENCE_AFTER()  asm volatile("tcgen05.fence::after_thread_sync;" ::: "memory")
#define TC_WAIT_LD() asm volatile("tcgen05.wait::ld.sync.aligned;" ::: "memory")
#define TC_WAIT_ST() asm volatile("tcgen05.wait::st.sync.aligned;" ::: "memory")
#define FENCE_PROXY() asm volatile("fence.proxy.async.shared::cta;" ::: "memory")

#define TCLD32(r, adr) \
    asm volatile( \
        "tcgen05.ld.sync.aligned.32x32b.x32.b32 " \
        "{%0, %1, %2, %3, %4, %5, %6, %7, %8, %9, %10, %11, %12, %13, %14, %15, " \
        " %16, %17, %18, %19, %20, %21, %22, %23, %24, %25, %26, %27, %28, %29, %30, %31}, [%32];" \
        : "=r"((r)[0]),  "=r"((r)[1]),  "=r"((r)[2]),  "=r"((r)[3]), \
          "=r"((r)[4]),  "=r"((r)[5]),  "=r"((r)[6]),  "=r"((r)[7]), \
          "=r"((r)[8]),  "=r"((r)[9]),  "=r"((r)[10]), "=r"((r)[11]), \
          "=r"((r)[12]), "=r"((r)[13]), "=r"((r)[14]), "=r"((r)[15]), \
          "=r"((r)[16]), "=r"((r)[17]), "=r"((r)[18]), "=r"((r)[19]), \
          "=r"((r)[20]), "=r"((r)[21]), "=r"((r)[22]), "=r"((r)[23]), \
          "=r"((r)[24]), "=r"((r)[25]), "=r"((r)[26]), "=r"((r)[27]), \
          "=r"((r)[28]), "=r"((r)[29]), "=r"((r)[30]), "=r"((r)[31]) \
        : "r"(adr))

#define TCST2(adr, r0, r1) \
    asm volatile("tcgen05.st.sync.aligned.32x32b.x2.b32 [%0], {%1, %2};" \
                 :: "r"(adr), "r"(r0), "r"(r1) : "memory")

__device__ __forceinline__ void mma_tf32(uint32_t d, uint64_t a, uint64_t b, uint32_t en) {
    asm volatile(
        "{\n\t.reg .pred p;\n\tsetp.ne.u32 p, %4, 0;\n\t"
        "tcgen05.mma.cta_group::1.kind::tf32 [%0], %1, %2, %3, {%5, %5, %5, %5}, p;\n\t}"
        :: "r"(d), "l"(a), "l"(b), "r"(IDESC), "r"(en), "r"(0u) : "memory");
}
#endif  // TC_PATH

// ================= fallback fp32 microkernel (compiled always; dead on sm_103a) =================
template<int SHIFT>
__device__ __forceinline__ void gemm_tap(float C[8][8], const float* __restrict__ Wt,
                                         const float* __restrict__ B, int m0, int n0)
{
    const float* brow = B + PAD + n0 + SHIFT;
    const float* wrow = Wt + m0;
    #pragma unroll 2
    for (int k = 0; k < HID; ++k) {
        float a[8], bb[8];
        float4 a0 = *(const float4*)(wrow);
        float4 a1 = *(const float4*)(wrow + 4);
        a[0]=a0.x; a[1]=a0.y; a[2]=a0.z; a[3]=a0.w;
        a[4]=a1.x; a[5]=a1.y; a[6]=a1.z; a[7]=a1.w;
        #pragma unroll
        for (int j = 0; j < 8; ++j) bb[j] = brow[j];
        #pragma unroll
        for (int i = 0; i < 8; ++i)
            #pragma unroll
            for (int j = 0; j < 8; ++j)
                C[i][j] += a[i] * bb[j];
        wrow += HID;
        brow += XS;
    }
}

// ------------------------------------------------------------------
// Main kernel. smem (floats, 1KB-aligned base):
//   Bt@0 (16384) | A ring @16384 (4 x 8192 = 32768) | Par@49152 (1280)
//   | RedS@50432 (256) | RedQ@50688 (256) | Svec@50944 (128) | misc bytes @204288
// ------------------------------------------------------------------
#define SMF_ARING 16384
#define SMF_PAR   49152
#define SMF_REDS  50432
#define SMF_REDQ  50688
#define SMF_SVEC  50944
#define SMB_MISC  204288
#define SMEM_TOTAL 205504

__global__ __launch_bounds__(256, 1) void k_main(
    const int* __restrict__ nidx, const int* __restrict__ nlen,
    const float* __restrict__ ssmB, const float* __restrict__ convB,
    const float* __restrict__ lnW, const float* __restrict__ lnB,
    const float* __restrict__ outW, const float* __restrict__ outB)
{
    extern __shared__ float smf[];
    const int n = blockIdx.x;
    const int tid = threadIdx.x;
    const int len = nlen[n];

#if TC_PATH
    uint32_t raw = smem_u32(smf);
    uint32_t sbase = (raw + 1023u) & ~1023u;
    float* bas = smf + (sbase - raw) / 4;

    float* Bt   = bas;
    float* Par  = bas + SMF_PAR;
    float* RedS = bas + SMF_REDS;
    float* RedQ = bas + SMF_REDQ;
    float* Svec = bas + SMF_SVEC;
    uint32_t Baddr = sbase;
    uint32_t miscb = sbase + SMB_MISC;        // tmem ptr @+0
    uint32_t mb_tma0 = miscb + 8;             // 4 barriers
    uint32_t mb_mma0 = miscb + 40;            // 4 barriers
    uint32_t mb_grp  = miscb + 72;

    const int w = tid >> 5, lane = tid & 31;
    const int h = w >> 2;                  // column half
    const int c = (w & 3) * 32 + lane;     // channel (TMEM row) owned
    const uint32_t woff = (uint32_t)(w & 3) << 21;

    if (tid == 0) {
        #pragma unroll
        for (int s = 0; s < NSLOT; ++s) {
            MBAR_INIT(mb_tma0 + 8 * s, 1);
            MBAR_INIT(mb_mma0 + 8 * s, 1);
        }
        MBAR_INIT(mb_grp, 1);
    }
    for (int e = tid; e < 128; e += 256) Par[e] = ssmB[e];
    for (int e = tid; e < 384; e += 256) Par[128 + e] = convB[e];
    for (int e = tid; e < 384; e += 256) Par[512 + e] = lnW[e];
    for (int e = tid; e < 384; e += 256) Par[896 + e] = lnB[e];
    if (w == 0) TC_ALLOC(miscb, 512);
    __syncthreads();
    uint32_t tmem;
    asm("ld.shared.b32 %0, [%1];" : "=r"(tmem) : "r"(miscb));
    if (w == 0) TC_RELINQ();

    // chunk order: 20 chunks = 10 taps x 2 half-tiles (32KB, K=64, 8 MMAs each)
    // chunk cchunk: tap = c>>1, half = c&1; gmem src = TSEQ[tap]*16384 + half*8192 floats
    // preload chunks 0..3 into ring slots 0..3  (taps 0 and 1; TSEQ[0]=0, TSEQ[1]=1)
    if (tid == 0) {
        #pragma unroll
        for (int s = 0; s < NSLOT; ++s) {
            int tile = (s >> 1);           // chunks 0,1 -> tile 0; chunks 2,3 -> tile 1
            int half = s & 1;
            MBAR_EXPECT(mb_tma0 + 8 * s, 32768);
            bulk_g2s(sbase + (uint32_t)(SMF_ARING + s * 8192) * 4u,
                     g_Wswz + tile * 16384 + half * 8192, 32768, mb_tma0 + 8 * s);
        }
    }

    // gather masked neighbor rows: B[l][k] = H[idx[l]][k]
    const int* idxrow = nidx + n * MAXL;
    for (int e = tid; e < MAXL * HID; e += 256) {
        int l = e >> 7, k = e & 127;
        float v = 0.f;
        if (l < len) v = g_H[idxrow[l] * HID + k];
        *(float*)((char*)Bt + swz_off(l, k)) = tf32r(v);
    }

    // zero margin columns of side windows: SA..SA+1 and SB+130..SB+131 (all 128 rows)
    if (h == 0) {
        uint32_t tb = tmem + woff;
        TCST2(tb + SA, 0u, 0u);
        TCST2(tb + SB + 130, 0u, 0u);
        TC_WAIT_ST();
        TC_FENCE_BEFORE();
    }

    int q = 0;
    uint32_t va[32], vb[32];

    for (int stage = 0; stage < 4; ++stage) {
        __syncthreads();   // B tile ready; TMEM stores visible

        if (tid == 0) {
            // per-tap: weight tile, D write base, overwrite-on-first-chunk flag
            const int TSEQ[10] = {0, 1, 2, 3, 5, 4, 6, 8, 7, 9};
            const int DBASE[10]= {D0, SA + 2, D0, SB + 2, D0, D0 + 2, D0 - 2, D0, D0 + 4, D0 - 4};
            const int INITT[10]= {1, 1, 1, 1, 1, 0, 0, 1, 0, 0};
            FENCE_PROXY();
            TC_FENCE_AFTER();
            uint64_t bd0 = DESC_BASE | ((uint64_t)((Baddr >> 4) & 0x3FFFu));
            int qe = 2 + 6 * stage;
            for (; q < qe; ++q) {
                int tap = q >> 1, half = q & 1;
                int slot = q % NSLOT, ph = (q / NSLOT) & 1;
                mbar_wait(mb_tma0 + 8 * slot, ph);
                uint32_t aaddr = sbase + (uint32_t)(SMF_ARING + slot * 8192) * 4u;
                uint64_t ad = DESC_BASE | ((uint64_t)((aaddr >> 4) & 0x3FFFu));
                uint64_t bd = bd0 + (uint64_t)(half * 2048);
                uint32_t dadr = tmem + (uint32_t)DBASE[tap];
                #pragma unroll
                for (int ks = 0; ks < 8; ++ks) {
                    uint64_t o = (uint64_t)((ks >> 2) * 1024 + (ks & 3) * 2);
                    uint32_t en = (ks == 0 && half == 0 && INITT[tap]) ? 0u : 1u;
                    mma_tf32(dadr, ad + o, bd + o, en);
                }
                TC_COMMIT(mb_mma0 + 8 * slot);
                // lag-3 prefetch: chunk q+3 into slot (q+3)%4 == (q-1)%4 — that chunk's
                // MMAs drained while we waited q's TMA, so this wait is ~free.
                int cN = q + 3;
                if (q >= 1 && cN < NCHUNK) {
                    int rs = cN % NSLOT;
                    int rph = ((q - 1) / NSLOT) & 1;
                    mbar_wait(mb_mma0 + 8 * rs, rph);
                    const float* src = g_Wswz + TSEQ[cN >> 1] * 16384 + (cN & 1) * 8192;
                    MBAR_EXPECT(mb_tma0 + 8 * rs, 32768);
                    bulk_g2s(sbase + (uint32_t)(SMF_ARING + rs * 8192) * 4u, src, 32768,
                             mb_tma0 + 8 * rs);
                }
            }
            TC_COMMIT(mb_grp);   // fires when ALL prior MMAs of this CTA complete
        }
        mbar_wait(mb_grp, stage & 1);
        TC_FENCE_AFTER();

        // ---- epilogue: read D window (plus side windows at stage 1) ----
        TCLD32(va, tmem + woff + (uint32_t)(D0 + 64 * h));
        TCLD32(vb, tmem + woff + (uint32_t)(D0 + 64 * h + 32));
        if (stage == 1) {
            uint32_t ta[32], tb2[32];
            TCLD32(ta,  tmem + woff + (uint32_t)(SA + 1 + 64 * h));
            TCLD32(tb2, tmem + woff + (uint32_t)(SA + 1 + 64 * h + 32));
            TC_WAIT_LD();
            #pragma unroll
            for (int j = 0; j < 32; ++j) {
                va[j] = __float_as_uint(__uint_as_float(va[j]) + __uint_as_float(ta[j]));
                vb[j] = __float_as_uint(__uint_as_float(vb[j]) + __uint_as_float(tb2[j]));
            }
            TCLD32(ta,  tmem + woff + (uint32_t)(SB + 3 + 64 * h));
            TCLD32(tb2, tmem + woff + (uint32_t)(SB + 3 + 64 * h + 32));
            TC_WAIT_LD();
            #pragma unroll
            for (int j = 0; j < 32; ++j) {
                va[j] = __float_as_uint(__uint_as_float(va[j]) + __uint_as_float(ta[j]));
                vb[j] = __float_as_uint(__uint_as_float(vb[j]) + __uint_as_float(tb2[j]));
            }
        } else {
            TC_WAIT_LD();
        }

        if (stage == 0) {
            float bv = Par[c];
            #pragma unroll
            for (int j = 0; j < 32; ++j) {
                int l = 64 * h + j;
                *(float*)((char*)Bt + swz_off(l, c)) = tf32r(__uint_as_float(va[j]) + bv);
            }
            #pragma unroll
            for (int j = 0; j < 32; ++j) {
                int l = 64 * h + 32 + j;
                *(float*)((char*)Bt + swz_off(l, c)) = tf32r(__uint_as_float(vb[j]) + bv);
            }
        } else {
            int layer = stage - 1;
            float bv = Par[128 + layer * 128 + c];
            float s = 0.f, q2 = 0.f;
            #pragma unroll
            for (int j = 0; j < 32; ++j) {
                float z = gelu_exact(__uint_as_float(va[j]) + bv);
                va[j] = __float_as_uint(z); s += z; q2 += z * z;
            }
            #pragma unroll
            for (int j = 0; j < 32; ++j) {
                float z = gelu_exact(__uint_as_float(vb[j]) + bv);
                vb[j] = __float_as_uint(z); s += z; q2 += z * z;
            }
            RedS[h * 128 + c] = s;
            RedQ[h * 128 + c] = q2;
            __syncthreads();
            float st = s + RedS[(h ^ 1) * 128 + c];
            float qt = q2 + RedQ[(h ^ 1) * 128 + c];
            float m   = st * (1.f / 128.f);
            float inv = rsqrtf(qt * (1.f / 128.f) - m * m + EPS);
            const float* lw = Par + 512 + layer * 128;
            const float* lb = Par + 896 + layer * 128;
            if (stage < 3) {
                #pragma unroll
                for (int j = 0; j < 32; ++j) {
                    int l = 64 * h + j;
                    float o = (__uint_as_float(va[j]) - m) * inv * lw[l] + lb[l];
                    *(float*)((char*)Bt + swz_off(l, c)) = tf32r(o);
                }
                #pragma unroll
                for (int j = 0; j < 32; ++j) {
                    int l = 64 * h + 32 + j;
                    float o = (__uint_as_float(vb[j]) - m) * inv * lw[l] + lb[l];
                    *(float*)((char*)Bt + swz_off(l, c)) = tf32r(o);
                }
            } else {
                float ms = 0.f;
                #pragma unroll
                for (int j = 0; j < 32; ++j) {
                    int l = 64 * h + j;
                    float o = (__uint_as_float(va[j]) - m) * inv * lw[l] + lb[l];
                    if (l < len) ms += o;
                }
                #pragma unroll
                for (int j = 0; j < 32; ++j) {
                    int l = 64 * h + 32 + j;
                    float o = (__uint_as_float(vb[j]) - m) * inv * lw[l] + lb[l];
                    if (l < len) ms += o;
                }
                __syncthreads();
                RedS[h * 128 + c] = ms;
                __syncthreads();
                if (h == 0) Svec[c] = RedS[c] + RedS[128 + c];
                __syncthreads();
                if (tid < 128) {
                    float acc = 0.f;
                    #pragma unroll 8
                    for (int cc = 0; cc < 128; ++cc)
                        acc += Svec[cc] * outW[cc * 128 + tid];
                    float cnt = (float)len, denom = fmaxf(cnt, 1.f);
                    g_pooled[n * 128 + tid] = (acc + cnt * outB[tid]) / denom;
                }
            }
        }
    }
    __syncthreads();
    if (w == 0) TC_DEALLOC(tmem, 512);

#else  // ===================== fp32 fallback body (dead on sm_103a device) =====================
    float* Xa   = smf;
    float* Xb   = smf + HID * XS;
    float* Wt   = smf + 2 * HID * XS;
    float* svec = Wt + HID * HID;

    const int tx = tid & 15, ty = tid >> 4;
    const int m0 = ty * 8, n0 = tx * 8;

    for (int e = tid; e < HID * 8; e += 256) {
        int r = e >> 3, p = e & 7;
        int col = (p < PAD) ? p : (XS - 8 + p);
        Xa[r * XS + col] = 0.f;
        Xb[r * XS + col] = 0.f;
    }
    const int* idxrow = nidx + n * MAXL;
    for (int e = tid; e < MAXL * HID; e += 256) {
        int l = e >> 7, k = e & (HID - 1);
        float v = 0.f;
        if (l < len) v = g_H[idxrow[l] * HID + k];
        Xa[k * XS + PAD + l] = v;
    }
    for (int e = tid; e < HID * HID; e += 256) Wt[e] = g_Wplain[e];
    __syncthreads();

    float C[8][8];
    #pragma unroll
    for (int i = 0; i < 8; ++i)
        #pragma unroll
        for (int j = 0; j < 8; ++j) C[i][j] = 0.f;
    gemm_tap<0>(C, Wt, Xa, m0, n0);
    #pragma unroll
    for (int i = 0; i < 8; ++i) {
        float bv = ssmB[m0 + i];
        #pragma unroll
        for (int j = 0; j < 8; ++j)
            Xb[(m0 + i) * XS + PAD + n0 + j] = C[i][j] + bv;
    }
    __syncthreads();

    float* src = Xb;
    float* dst = Xa;
    for (int layer = 0; layer < 3; ++layer) {
        const int d = 1 << layer;
        #pragma unroll
        for (int i = 0; i < 8; ++i)
            #pragma unroll
            for (int j = 0; j < 8; ++j) C[i][j] = 0.f;
        for (int kk = 0; kk < 3; ++kk) {
            const float* wsrc = g_Wplain + (1 + layer * 3 + kk) * (HID * HID);
            for (int e = tid; e < HID * HID; e += 256) Wt[e] = wsrc[e];
            __syncthreads();
            int shift = (kk - 1) * d;
            switch (shift) {
                case -4: gemm_tap<-4>(C, Wt, src, m0, n0); break;
                case -2: gemm_tap<-2>(C, Wt, src, m0, n0); break;
                case -1: gemm_tap<-1>(C, Wt, src, m0, n0); break;
                case  0: gemm_tap< 0>(C, Wt, src, m0, n0); break;
                case  1: gemm_tap< 1>(C, Wt, src, m0, n0); break;
                case  2: gemm_tap< 2>(C, Wt, src, m0, n0); break;
                default: gemm_tap< 4>(C, Wt, src, m0, n0); break;
            }
            __syncthreads();
        }
        float rs[8], rq[8];
        #pragma unroll
        for (int i = 0; i < 8; ++i) {
            float bv = convB[layer * HID + m0 + i];
            rs[i] = 0.f; rq[i] = 0.f;
            #pragma unroll
            for (int j = 0; j < 8; ++j) {
                float z = gelu_exact(C[i][j] + bv);
                C[i][j] = z; rs[i] += z; rq[i] += z * z;
            }
        }
        #pragma unroll
        for (int i = 0; i < 8; ++i) {
            #pragma unroll
            for (int off = 8; off; off >>= 1) {
                rs[i] += __shfl_xor_sync(0xffffffffu, rs[i], off);
                rq[i] += __shfl_xor_sync(0xffffffffu, rq[i], off);
            }
        }
        float lw[8], lb[8];
        #pragma unroll
        for (int j = 0; j < 8; ++j) {
            lw[j] = lnW[layer * HID + n0 + j];
            lb[j] = lnB[layer * HID + n0 + j];
        }
        if (layer < 2) {
            #pragma unroll
            for (int i = 0; i < 8; ++i) {
                float m   = rs[i] * (1.f / MAXL);
                float inv = rsqrtf(rq[i] * (1.f / MAXL) - m * m + EPS);
                #pragma unroll
                for (int j = 0; j < 8; ++j)
                    dst[(m0 + i) * XS + PAD + n0 + j] = (C[i][j] - m) * inv * lw[j] + lb[j];
            }
            float* t = src; src = dst; dst = t;
            __syncthreads();
        } else {
            float ms[8];
            #pragma unroll
            for (int i = 0; i < 8; ++i) {
                float m   = rs[i] * (1.f / MAXL);
                float inv = rsqrtf(rq[i] * (1.f / MAXL) - m * m + EPS);
                ms[i] = 0.f;
                #pragma unroll
                for (int j = 0; j < 8; ++j) {
                    float o = (C[i][j] - m) * inv * lw[j] + lb[j];
                    if (n0 + j < len) ms[i] += o;
                }
            }
            #pragma unroll
            for (int i = 0; i < 8; ++i) {
                #pragma unroll
                for (int off = 8; off; off >>= 1)
                    ms[i] += __shfl_xor_sync(0xffffffffu, ms[i], off);
            }
            if (tx == 0) {
                #pragma unroll
                for (int i = 0; i < 8; ++i) svec[m0 + i] = ms[i];
            }
        }
    }
    __syncthreads();
    if (tid < HID) {
        float acc = 0.f;
        #pragma unroll 8
        for (int cc = 0; cc < HID; ++cc)
            acc += svec[cc] * outW[cc * HID + tid];
        float cnt   = (float)len;
        float denom = fmaxf(cnt, 1.f);
        g_pooled[n * HID + tid] = (acc + cnt * outB[tid]) / denom;
    }
#endif
}

// ------------------------------------------------------------------
// Classifier head
// ------------------------------------------------------------------
__global__ __launch_bounds__(64) void k_cls(
    const float* __restrict__ W1, const float* __restrict__ b1,
    const float* __restrict__ W2, const float* __restrict__ b2,
    float* __restrict__ out)
{
    __shared__ float p[HID];
    __shared__ float g[64];
    int n = blockIdx.x;
    int j = threadIdx.x;
    p[j]      = g_pooled[n * HID + j];
    p[j + 64] = g_pooled[n * HID + j + 64];
    __syncthreads();
    float acc = b1[j];
    #pragma unroll 8
    for (int cc = 0; cc < HID; ++cc)
        acc += p[cc] * W1[cc * 64 + j];
    g[j] = gelu_exact(acc);
    __syncthreads();
    float acc2 = b2[j];
    #pragma unroll 8
    for (int t = 0; t < 64; ++t)
        acc2 += g[t] * W2[t * 64 + j];
    out[n * NCLS + j] = acc2;
}

// ------------------------------------------------------------------
extern "C" void kernel_launch(void* const* d_in, const int* in_sizes, int n_in,
                              void* d_out, int out_size)
{
    (void)in_sizes; (void)n_in; (void)out_size;
    const float* node_feat  = (const float*)d_in[0];
    const int*   nidx       = (const int*)  d_in[1];
    const int*   nlen       = (const int*)  d_in[2];
    const float* local_W    = (const float*)d_in[3];
    const float* local_b    = (const float*)d_in[4];
    const float* local_ln_w = (const float*)d_in[5];
    const float* local_ln_b = (const float*)d_in[6];
    const float* ssm_in_W   = (const float*)d_in[7];
    const float* ssm_in_b   = (const float*)d_in[8];
    const float* conv_w     = (const float*)d_in[9];
    const float* conv_b     = (const float*)d_in[10];
    const float* ln_w       = (const float*)d_in[11];
    const float* ln_b       = (const float*)d_in[12];
    const float* out_W      = (const float*)d_in[13];
    const float* out_b      = (const float*)d_in[14];
    const float* cls_W1     = (const float*)d_in[15];
    const float* cls_b1     = (const float*)d_in[16];
    const float* cls_W2     = (const float*)d_in[17];
    const float* cls_b2     = (const float*)d_in[18];
    float* out = (float*)d_out;

    cudaFuncSetAttribute(k_main, cudaFuncAttributeMaxDynamicSharedMemorySize, SMEM_TOTAL);

    k_prep<<<(10 * HID * HID + 255) / 256, 256>>>(ssm_in_W, conv_w);
    k_local8<<<N_NODES / 8, 128>>>(node_feat, local_W, local_b, local_ln_w, local_ln_b);
    k_main<<<N_NODES, 256, SMEM_TOTAL>>>(nidx, nlen, ssm_in_b, conv_b, ln_w, ln_b, out_W, out_b);
    k_cls<<<N_NODES, 64>>>(cls_W1, cls_b1, cls_W2, cls_b2, out);
}

// round 11
// speedup vs baseline: 1.8089x; 1.0154x over previous
#include <cuda_runtime.h>
#include <cstdint>

#if defined(__CUDA_ARCH_FEAT_SM103_ALL) || \
    (defined(__CUDA_ARCH_SPECIFIC__) && (__CUDA_ARCH_SPECIFIC__ == 1030)) || \
    (defined(__CUDA_ARCH_FAMILY_SPECIFIC__) && (__CUDA_ARCH_FAMILY_SPECIFIC__ == 1030))
#define TC_PATH 1
#else
#define TC_PATH 0
#endif

#define N_NODES 16384
#define IN_DIM 256
#define HID 128
#define MAXL 128
#define NCLS 64
#define EPS 1e-5f
#define D0 4            // center window cols 0..135 (even write bases only)
#define SA 144          // layer-0 shift -1 window (write SA+2, read SA+1)
#define SB 276          // layer-0 shift +1 window (write SB+2, read SB+3)
#define PAD 4
#define XS (MAXL + 2*PAD)
#define NSLOT 4         // TMA ring depth (32KB chunks)
#define NCHUNK 20       // 10 taps x 2 half-tiles

// ---------------- device scratch (no allocations allowed) ----------------
__device__ float g_H[N_NODES * HID];
__device__ float g_pooled[N_NODES * HID];
__device__ float g_Wswz[10 * HID * HID];    // swizzled tf32 tiles (tensor path)
__device__ float g_Wplain[10 * HID * HID];  // plain tiles (fallback path)

// idesc kind::tf32: dtype F32(1<<4), atype TF32(2<<7), btype TF32(2<<10), N=128(16<<17), M=128(8<<24)
static constexpr uint32_t IDESC =
    (1u << 4) | (2u << 7) | (2u << 10) | (16u << 17) | (8u << 24);
// SW128 K-major smem descriptor: layout=2, version=1, SBO=64 (1024B), LBO=1 (16B)
static constexpr uint64_t DESC_BASE =
    (uint64_t(2) << 61) | (uint64_t(1) << 46) | (uint64_t(64) << 32) | (uint64_t(1) << 16);

__device__ __forceinline__ float gelu_exact(float x) {
    return 0.5f * x * (1.0f + erff(x * 0.7071067811865476f));
}
__device__ __forceinline__ float tf32r(float x) {
    uint32_t u;
    asm("cvt.rna.tf32.f32 %0, %1;" : "=r"(u) : "f"(x));
    return __uint_as_float(u);
}
__device__ __forceinline__ uint32_t smem_u32(const void* p) {
    uint32_t a;
    asm("{ .reg .u64 t; cvta.to.shared.u64 t, %1; cvt.u32.u64 %0, t; }" : "=r"(a) : "l"(p));
    return a;
}
// byte offset of (row, col) in a [128 x 128 fp32] K-major SW128 blocked tile
__device__ __forceinline__ uint32_t swz_off(int row, int col) {
    uint32_t off = ((uint32_t)(row >> 3) + (uint32_t)(col >> 5) * 16u) * 1024u
                 + (uint32_t)(row & 7) * 128u + (uint32_t)(col & 31) * 4u;
    return off ^ ((off >> 3) & 0x70u);
}

// ------------------------------------------------------------------
// Prep: weight tiles in both forms.
// tile 0: A[c][k] = ssm_in_W[k][c]; tiles 1..9: A[co][ci] = conv_w[layer][co][ci][kk]
// ------------------------------------------------------------------
__global__ void k_prep(const float* __restrict__ ssmW, const float* __restrict__ convW) {
    int e = blockIdx.x * blockDim.x + threadIdx.x;
    if (e >= 10 * HID * HID) return;
    int tile = e >> 14;
    int r = (e >> 7) & 127;
    int k = e & 127;
    float v;
    if (tile == 0) {
        v = ssmW[k * HID + r];
    } else {
        int t = tile - 1, layer = t / 3, kk = t % 3;
        v = convW[((layer * HID + r) * HID + k) * 3 + kk];
    }
    g_Wplain[tile * (HID * HID) + k * HID + r] = v;
    *(float*)((char*)(g_Wswz + tile * (HID * HID)) + swz_off(r, k)) = tf32r(v);
}

// ------------------------------------------------------------------
// Local encoder, 8 nodes per block
// ------------------------------------------------------------------
__global__ __launch_bounds__(128) void k_local8(
    const float* __restrict__ feat, const float* __restrict__ W,
    const float* __restrict__ b, const float* __restrict__ lnw,
    const float* __restrict__ lnb)
{
    __shared__ float xs[8 * IN_DIM];
    __shared__ float reds[32], redq[32];
    int base = blockIdx.x * 8;
    int c = threadIdx.x;
    for (int e = c; e < 8 * IN_DIM; e += 128)
        xs[e] = feat[base * IN_DIM + e];
    __syncthreads();

    float acc[8];
    float bb = b[c];
    #pragma unroll
    for (int nb = 0; nb < 8; ++nb) acc[nb] = bb;
    for (int i = 0; i < IN_DIM; ++i) {
        float wv = W[i * HID + c];
        #pragma unroll
        for (int nb = 0; nb < 8; ++nb) acc[nb] += xs[nb * IN_DIM + i] * wv;
    }
    int warp = c >> 5, lane = c & 31;
    float v[8];
    #pragma unroll
    for (int nb = 0; nb < 8; ++nb) {
        v[nb] = gelu_exact(acc[nb]);
        float s = v[nb], q = v[nb] * v[nb];
        #pragma unroll
        for (int off = 16; off; off >>= 1) {
            s += __shfl_xor_sync(0xffffffffu, s, off);
            q += __shfl_xor_sync(0xffffffffu, q, off);
        }
        if (lane == 0) { reds[warp * 8 + nb] = s; redq[warp * 8 + nb] = q; }
    }
    __syncthreads();
    #pragma unroll
    for (int nb = 0; nb < 8; ++nb) {
        float s = reds[nb] + reds[8 + nb] + reds[16 + nb] + reds[24 + nb];
        float q = redq[nb] + redq[8 + nb] + redq[16 + nb] + redq[24 + nb];
        float m = s * (1.f / HID);
        float inv = rsqrtf(q * (1.f / HID) - m * m + EPS);
        g_H[(base + nb) * HID + c] = (v[nb] - m) * inv * lnw[c] + lnb[c];
    }
}

// ================= tensor-path helpers (guarded) =================
#if TC_PATH
#define MBAR_INIT(a, cnt) \
    asm volatile("mbarrier.init.shared.b64 [%0], %1;" :: "r"(a), "r"((uint32_t)(cnt)) : "memory")
#define MBAR_EXPECT(a, bytes) \
    asm volatile("mbarrier.arrive.expect_tx.shared.b64 _, [%0], %1;" :: "r"(a), "r"((uint32_t)(bytes)) : "memory")
#define MBAR_ARRIVE(a) \
    asm volatile("mbarrier.arrive.shared.b64 _, [%0];" :: "r"(a) : "memory")

__device__ __forceinline__ void mbar_wait(uint32_t mbar, int parity) {
    asm volatile(
        "{\n\t.reg .pred P1;\n\t"
        "WL_%=:\n\t"
        "mbarrier.try_wait.parity.acquire.cta.shared::cta.b64 P1, [%0], %1, 0x989680;\n\t"
        "@P1 bra.uni WD_%=;\n\t"
        "bra.uni WL_%=;\n\t"
        "WD_%=:\n\t}"
        :: "r"(mbar), "r"((uint32_t)parity) : "memory");
}
__device__ __forceinline__ void bulk_g2s(uint32_t dst, const void* src, uint32_t bytes, uint32_t mbar) {
    asm volatile(
        "cp.async.bulk.shared::cluster.global.mbarrier::complete_tx::bytes [%0], [%1], %2, [%3];"
        :: "r"(dst), "l"(src), "r"(bytes), "r"(mbar) : "memory");
}

#define TC_ALLOC(sa, n) \
    asm volatile("tcgen05.alloc.cta_group::1.sync.aligned.shared::cta.b32 [%0], %1;" :: "r"(sa), "r"((uint32_t)(n)) : "memory")
#define TC_RELINQ() \
    asm volatile("tcgen05.relinquish_alloc_permit.cta_group::1.sync.aligned;")
#define TC_DEALLOC(t, n) \
    asm volatile("tcgen05.dealloc.cta_group::1.sync.aligned.b32 %0, %1;" :: "r"(t), "r"((uint32_t)(n)))
#define TC_COMMIT(mb) \
    asm volatile("tcgen05.commit.cta_group::1.mbarrier::arrive::one.shared::cluster.b64 [%0];" :: "r"(mb) : "memory")
#define TC_FENCE_BEFORE() asm volatile("tcgen05.fence::before_thread_sync;" ::: "memory")
#define TC_FENCE_AFTER()  asm volatile("tcgen05.fence::after_thread_sync;" ::: "memory")
#define TC_WAIT_LD() asm volatile("tcgen05.wait::ld.sync.aligned;" ::: "memory")
#define TC_WAIT_ST() asm volatile("tcgen05.wait::st.sync.aligned;" ::: "memory")
#define FENCE_PROXY() asm volatile("fence.proxy.async.shared::cta;" ::: "memory")
#define BAR_W() asm volatile("bar.sync 1, 256;" ::: "memory")

#define TCLD32(r, adr) \
    asm volatile( \
        "tcgen05.ld.sync.aligned.32x32b.x32.b32 " \
        "{%0, %1, %2, %3, %4, %5, %6, %7, %8, %9, %10, %11, %12, %13, %14, %15, " \
        " %16, %17, %18, %19, %20, %21, %22, %23, %24, %25, %26, %27, %28, %29, %30, %31}, [%32];" \
        : "=r"((r)[0]),  "=r"((r)[1]),  "=r"((r)[2]),  "=r"((r)[3]), \
          "=r"((r)[4]),  "=r"((r)[5]),  "=r"((r)[6]),  "=r"((r)[7]), \
          "=r"((r)[8]),  "=r"((r)[9]),  "=r"((r)[10]), "=r"((r)[11]), \
          "=r"((r)[12]), "=r"((r)[13]), "=r"((r)[14]), "=r"((r)[15]), \
          "=r"((r)[16]), "=r"((r)[17]), "=r"((r)[18]), "=r"((r)[19]), \
          "=r"((r)[20]), "=r"((r)[21]), "=r"((r)[22]), "=r"((r)[23]), \
          "=r"((r)[24]), "=r"((r)[25]), "=r"((r)[26]), "=r"((r)[27]), \
          "=r"((r)[28]), "=r"((r)[29]), "=r"((r)[30]), "=r"((r)[31]) \
        : "r"(adr))

#define TCST2(adr, r0, r1) \
    asm volatile("tcgen05.st.sync.aligned.32x32b.x2.b32 [%0], {%1, %2};" \
                 :: "r"(adr), "r"(r0), "r"(r1) : "memory")

__device__ __forceinline__ void mma_tf32(uint32_t d, uint64_t a, uint64_t b, uint32_t en) {
    asm volatile(
        "{\n\t.reg .pred p;\n\tsetp.ne.u32 p, %4, 0;\n\t"
        "tcgen05.mma.cta_group::1.kind::tf32 [%0], %1, %2, %3, {%5, %5, %5, %5}, p;\n\t}"
        :: "r"(d), "l"(a), "l"(b), "r"(IDESC), "r"(en), "r"(0u) : "memory");
}
#endif  // TC_PATH

// ================= fallback fp32 microkernel (compiled always; dead on sm_103a) =================
template<int SHIFT>
__device__ __forceinline__ void gemm_tap(float C[8][8], const float* __restrict__ Wt,
                                         const float* __restrict__ B, int m0, int n0)
{
    const float* brow = B + PAD + n0 + SHIFT;
    const float* wrow = Wt + m0;
    #pragma unroll 2
    for (int k = 0; k < HID; ++k) {
        float a[8], bb[8];
        float4 a0 = *(const float4*)(wrow);
        float4 a1 = *(const float4*)(wrow + 4);
        a[0]=a0.x; a[1]=a0.y; a[2]=a0.z; a[3]=a0.w;
        a[4]=a1.x; a[5]=a1.y; a[6]=a1.z; a[7]=a1.w;
        #pragma unroll
        for (int j = 0; j < 8; ++j) bb[j] = brow[j];
        #pragma unroll
        for (int i = 0; i < 8; ++i)
            #pragma unroll
            for (int j = 0; j < 8; ++j)
                C[i][j] += a[i] * bb[j];
        wrow += HID;
        brow += XS;
    }
}

// ------------------------------------------------------------------
// Main kernel, 288 threads: warps 0-7 = epilogue workers, warp 8 = {issuer t0, refiller t1}.
// smem (floats, 1KB-aligned base):
//   Bt@0 (16384) | A ring @16384 (4 x 8192) | Par@49152 (1280)
//   | RedS@50432 | RedQ@50688 | Svec@50944 | misc bytes @204288
// ------------------------------------------------------------------
#define SMF_ARING 16384
#define SMF_PAR   49152
#define SMF_REDS  50432
#define SMF_REDQ  50688
#define SMF_SVEC  50944
#define SMB_MISC  204288
#define SMEM_TOTAL 205504

__global__ __launch_bounds__(288, 1) void k_main(
    const int* __restrict__ nidx, const int* __restrict__ nlen,
    const float* __restrict__ ssmB, const float* __restrict__ convB,
    const float* __restrict__ lnW, const float* __restrict__ lnB,
    const float* __restrict__ outW, const float* __restrict__ outB)
{
    extern __shared__ float smf[];
    const int n = blockIdx.x;
    const int tid = threadIdx.x;
    const int len = nlen[n];

#if TC_PATH
    uint32_t raw = smem_u32(smf);
    uint32_t sbase = (raw + 1023u) & ~1023u;
    float* bas = smf + (sbase - raw) / 4;

    float* Bt   = bas;
    float* Par  = bas + SMF_PAR;
    float* RedS = bas + SMF_REDS;
    float* RedQ = bas + SMF_REDQ;
    float* Svec = bas + SMF_SVEC;
    uint32_t Baddr = sbase;
    uint32_t miscb = sbase + SMB_MISC;        // tmem ptr @+0
    uint32_t mb_tma0  = miscb + 8;            // 4 barriers
    uint32_t mb_mma0  = miscb + 40;           // 4 barriers
    uint32_t mb_grp   = miscb + 72;
    uint32_t mb_bready= miscb + 80;

    const int w = tid >> 5, lane = tid & 31;
    const int h = w >> 2;                  // column half (workers)
    const int c = (w & 3) * 32 + lane;     // channel (TMEM row) owned (workers)
    const uint32_t woff = (uint32_t)(w & 3) << 21;

    if (tid == 0) {
        #pragma unroll
        for (int s = 0; s < NSLOT; ++s) {
            MBAR_INIT(mb_tma0 + 8 * s, 1);
            MBAR_INIT(mb_mma0 + 8 * s, 1);
        }
        MBAR_INIT(mb_grp, 1);
        MBAR_INIT(mb_bready, 1);
    }
    for (int e = tid; e < 128; e += 288) Par[e] = ssmB[e];
    for (int e = tid; e < 384; e += 288) Par[128 + e] = convB[e];
    for (int e = tid; e < 384; e += 288) Par[512 + e] = lnW[e];
    for (int e = tid; e < 384; e += 288) Par[896 + e] = lnB[e];
    if (w == 0) TC_ALLOC(miscb, 512);
    __syncthreads();
    uint32_t tmem;
    asm("ld.shared.b32 %0, [%1];" : "=r"(tmem) : "r"(miscb));
    if (w == 0) TC_RELINQ();

    // taps: 0=ssm; 1..3 = L0 kk0/kk1/kk2; 4..6 = L1 kk1/kk0/kk2; 7..9 = L2 kk1/kk0/kk2
    // chunk q: tap = q>>1, half = q&1; weight src = TSEQ[tap]*16384 + half*8192 floats

    if (tid == 256) {
        // ===================== t0: MMA issuer (never waits MMAs) =====================
        const int TSEQ[10] = {0, 1, 2, 3, 5, 4, 6, 8, 7, 9};
        const int DBASE[10]= {D0, SA + 2, D0, SB + 2, D0, D0 + 2, D0 - 2, D0, D0 + 4, D0 - 4};
        const int INITT[10]= {1, 1, 1, 1, 1, 0, 0, 1, 0, 0};
        (void)TSEQ;
        uint64_t bd0 = DESC_BASE | ((uint64_t)((Baddr >> 4) & 0x3FFFu));
        int q = 0;
        for (int stage = 0; stage < 4; ++stage) {
            mbar_wait(mb_bready, stage & 1);
            TC_FENCE_AFTER();
            int qe = 2 + 6 * stage;
            for (; q < qe; ++q) {
                int tap = q >> 1, half = q & 1;
                int slot = q & 3;
                mbar_wait(mb_tma0 + 8 * slot, (q >> 2) & 1);
                uint32_t aaddr = sbase + (uint32_t)(SMF_ARING + slot * 8192) * 4u;
                uint64_t ad = DESC_BASE | ((uint64_t)((aaddr >> 4) & 0x3FFFu));
                uint64_t bd = bd0 + (uint64_t)(half * 2048);
                uint32_t dadr = tmem + (uint32_t)DBASE[tap];
                #pragma unroll
                for (int ks = 0; ks < 8; ++ks) {
                    uint64_t o = (uint64_t)((ks >> 2) * 1024 + (ks & 3) * 2);
                    uint32_t en = (ks == 0 && half == 0 && INITT[tap]) ? 0u : 1u;
                    mma_tf32(dadr, ad + o, bd + o, en);
                }
                TC_COMMIT(mb_mma0 + 8 * slot);
            }
            TC_COMMIT(mb_grp);   // cumulative: fires when ALL prior MMAs complete
        }
    } else if (tid == 257) {
        // ===================== t1: TMA refiller (absorbs all MMA-drain waits) =====================
        const int TSEQ[10] = {0, 1, 2, 3, 5, 4, 6, 8, 7, 9};
        // preload chunks 0..3 into slots 0..3
        #pragma unroll
        for (int s = 0; s < NSLOT; ++s) {
            const float* src = g_Wswz + TSEQ[s >> 1] * 16384 + (s & 1) * 8192;
            MBAR_EXPECT(mb_tma0 + 8 * s, 32768);
            bulk_g2s(sbase + (uint32_t)(SMF_ARING + s * 8192) * 4u, src, 32768, mb_tma0 + 8 * s);
        }
        // refills: target chunk cN = r + NSLOT, after chunk r's MMAs drain its slot
        for (int r = 0; r < NCHUNK - NSLOT; ++r) {
            int s = r & 3;
            mbar_wait(mb_mma0 + 8 * s, (r >> 2) & 1);
            int cN = r + NSLOT;
            const float* src = g_Wswz + TSEQ[cN >> 1] * 16384 + (cN & 1) * 8192;
            MBAR_EXPECT(mb_tma0 + 8 * s, 32768);
            bulk_g2s(sbase + (uint32_t)(SMF_ARING + s * 8192) * 4u, src, 32768, mb_tma0 + 8 * s);
        }
    } else if (tid < 256) {
        // ===================== workers: gather, epilogues =====================
        // gather masked neighbor rows: B[l][k] = H[idx[l]][k]
        const int* idxrow = nidx + n * MAXL;
        for (int e = tid; e < MAXL * HID; e += 256) {
            int l = e >> 7, k = e & 127;
            float v = 0.f;
            if (l < len) v = g_H[idxrow[l] * HID + k];
            *(float*)((char*)Bt + swz_off(l, k)) = tf32r(v);
        }
        // zero margin columns of side windows (all 128 TMEM rows)
        if (h == 0) {
            uint32_t tb = tmem + woff;
            TCST2(tb + SA, 0u, 0u);
            TCST2(tb + SB + 130, 0u, 0u);
            TC_WAIT_ST();
            TC_FENCE_BEFORE();
        }
        BAR_W();
        if (tid == 0) { FENCE_PROXY(); MBAR_ARRIVE(mb_bready); }   // parity 0: stage-0 inputs ready

        uint32_t va[32], vb[32];
        for (int stage = 0; stage < 4; ++stage) {
            mbar_wait(mb_grp, stage & 1);
            TC_FENCE_AFTER();

            TCLD32(va, tmem + woff + (uint32_t)(D0 + 64 * h));
            TCLD32(vb, tmem + woff + (uint32_t)(D0 + 64 * h + 32));
            if (stage == 1) {
                uint32_t ta[32], tb2[32];
                TCLD32(ta,  tmem + woff + (uint32_t)(SA + 1 + 64 * h));
                TCLD32(tb2, tmem + woff + (uint32_t)(SA + 1 + 64 * h + 32));
                TC_WAIT_LD();
                #pragma unroll
                for (int j = 0; j < 32; ++j) {
                    va[j] = __float_as_uint(__uint_as_float(va[j]) + __uint_as_float(ta[j]));
                    vb[j] = __float_as_uint(__uint_as_float(vb[j]) + __uint_as_float(tb2[j]));
                }
                TCLD32(ta,  tmem + woff + (uint32_t)(SB + 3 + 64 * h));
                TCLD32(tb2, tmem + woff + (uint32_t)(SB + 3 + 64 * h + 32));
                TC_WAIT_LD();
                #pragma unroll
                for (int j = 0; j < 32; ++j) {
                    va[j] = __float_as_uint(__uint_as_float(va[j]) + __uint_as_float(ta[j]));
                    vb[j] = __float_as_uint(__uint_as_float(vb[j]) + __uint_as_float(tb2[j]));
                }
            } else {
                TC_WAIT_LD();
            }

            if (stage == 0) {
                float bv = Par[c];
                #pragma unroll
                for (int j = 0; j < 32; ++j) {
                    int l = 64 * h + j;
                    *(float*)((char*)Bt + swz_off(l, c)) = tf32r(__uint_as_float(va[j]) + bv);
                }
                #pragma unroll
                for (int j = 0; j < 32; ++j) {
                    int l = 64 * h + 32 + j;
                    *(float*)((char*)Bt + swz_off(l, c)) = tf32r(__uint_as_float(vb[j]) + bv);
                }
                BAR_W();
                if (tid == 0) { FENCE_PROXY(); MBAR_ARRIVE(mb_bready); }
            } else {
                int layer = stage - 1;
                float bv = Par[128 + layer * 128 + c];
                float s = 0.f, q2 = 0.f;
                #pragma unroll
                for (int j = 0; j < 32; ++j) {
                    float z = gelu_exact(__uint_as_float(va[j]) + bv);
                    va[j] = __float_as_uint(z); s += z; q2 += z * z;
                }
                #pragma unroll
                for (int j = 0; j < 32; ++j) {
                    float z = gelu_exact(__uint_as_float(vb[j]) + bv);
                    vb[j] = __float_as_uint(z); s += z; q2 += z * z;
                }
                RedS[h * 128 + c] = s;
                RedQ[h * 128 + c] = q2;
                BAR_W();
                float st = s + RedS[(h ^ 1) * 128 + c];
                float qt = q2 + RedQ[(h ^ 1) * 128 + c];
                float m   = st * (1.f / 128.f);
                float inv = rsqrtf(qt * (1.f / 128.f) - m * m + EPS);
                const float* lw = Par + 512 + layer * 128;
                const float* lb = Par + 896 + layer * 128;
                if (stage < 3) {
                    #pragma unroll
                    for (int j = 0; j < 32; ++j) {
                        int l = 64 * h + j;
                        float o = (__uint_as_float(va[j]) - m) * inv * lw[l] + lb[l];
                        *(float*)((char*)Bt + swz_off(l, c)) = tf32r(o);
                    }
                    #pragma unroll
                    for (int j = 0; j < 32; ++j) {
                        int l = 64 * h + 32 + j;
                        float o = (__uint_as_float(vb[j]) - m) * inv * lw[l] + lb[l];
                        *(float*)((char*)Bt + swz_off(l, c)) = tf32r(o);
                    }
                    BAR_W();
                    if (tid == 0) { FENCE_PROXY(); MBAR_ARRIVE(mb_bready); }
                } else {
                    float ms = 0.f;
                    #pragma unroll
                    for (int j = 0; j < 32; ++j) {
                        int l = 64 * h + j;
                        float o = (__uint_as_float(va[j]) - m) * inv * lw[l] + lb[l];
                        if (l < len) ms += o;
                    }
                    #pragma unroll
                    for (int j = 0; j < 32; ++j) {
                        int l = 64 * h + 32 + j;
                        float o = (__uint_as_float(vb[j]) - m) * inv * lw[l] + lb[l];
                        if (l < len) ms += o;
                    }
                    BAR_W();
                    RedS[h * 128 + c] = ms;
                    BAR_W();
                    if (h == 0) Svec[c] = RedS[c] + RedS[128 + c];
                    BAR_W();
                    if (tid < 128) {
                        float acc = 0.f;
                        #pragma unroll 8
                        for (int cc = 0; cc < 128; ++cc)
                            acc += Svec[cc] * outW[cc * 128 + tid];
                        float cnt = (float)len, denom = fmaxf(cnt, 1.f);
                        g_pooled[n * 128 + tid] = (acc + cnt * outB[tid]) / denom;
                    }
                }
            }
        }
    }
    __syncthreads();   // all 288 threads
    if (w == 0) TC_DEALLOC(tmem, 512);

#else  // ===================== fp32 fallback body (dead on sm_103a device) =====================
    if (tid >= 256) return;   // extra warp exits before any barrier

    float* Xa   = smf;
    float* Xb   = smf + HID * XS;
    float* Wt   = smf + 2 * HID * XS;
    float* svec = Wt + HID * HID;

    const int tx = tid & 15, ty = tid >> 4;
    const int m0 = ty * 8, n0 = tx * 8;

    for (int e = tid; e < HID * 8; e += 256) {
        int r = e >> 3, p = e & 7;
        int col = (p < PAD) ? p : (XS - 8 + p);
        Xa[r * XS + col] = 0.f;
        Xb[r * XS + col] = 0.f;
    }
    const int* idxrow = nidx + n * MAXL;
    for (int e = tid; e < MAXL * HID; e += 256) {
        int l = e >> 7, k = e & (HID - 1);
        float v = 0.f;
        if (l < len) v = g_H[idxrow[l] * HID + k];
        Xa[k * XS + PAD + l] = v;
    }
    for (int e = tid; e < HID * HID; e += 256) Wt[e] = g_Wplain[e];
    __syncthreads();

    float C[8][8];
    #pragma unroll
    for (int i = 0; i < 8; ++i)
        #pragma unroll
        for (int j = 0; j < 8; ++j) C[i][j] = 0.f;
    gemm_tap<0>(C, Wt, Xa, m0, n0);
    #pragma unroll
    for (int i = 0; i < 8; ++i) {
        float bv = ssmB[m0 + i];
        #pragma unroll
        for (int j = 0; j < 8; ++j)
            Xb[(m0 + i) * XS + PAD + n0 + j] = C[i][j] + bv;
    }
    __syncthreads();

    float* src = Xb;
    float* dst = Xa;
    for (int layer = 0; layer < 3; ++layer) {
        const int d = 1 << layer;
        #pragma unroll
        for (int i = 0; i < 8; ++i)
            #pragma unroll
            for (int j = 0; j < 8; ++j) C[i][j] = 0.f;
        for (int kk = 0; kk < 3; ++kk) {
            const float* wsrc = g_Wplain + (1 + layer * 3 + kk) * (HID * HID);
            for (int e = tid; e < HID * HID; e += 256) Wt[e] = wsrc[e];
            __syncthreads();
            int shift = (kk - 1) * d;
            switch (shift) {
                case -4: gemm_tap<-4>(C, Wt, src, m0, n0); break;
                case -2: gemm_tap<-2>(C, Wt, src, m0, n0); break;
                case -1: gemm_tap<-1>(C, Wt, src, m0, n0); break;
                case  0: gemm_tap< 0>(C, Wt, src, m0, n0); break;
                case  1: gemm_tap< 1>(C, Wt, src, m0, n0); break;
                case  2: gemm_tap< 2>(C, Wt, src, m0, n0); break;
                default: gemm_tap< 4>(C, Wt, src, m0, n0); break;
            }
            __syncthreads();
        }
        float rs[8], rq[8];
        #pragma unroll
        for (int i = 0; i < 8; ++i) {
            float bv = convB[layer * HID + m0 + i];
            rs[i] = 0.f; rq[i] = 0.f;
            #pragma unroll
            for (int j = 0; j < 8; ++j) {
                float z = gelu_exact(C[i][j] + bv);
                C[i][j] = z; rs[i] += z; rq[i] += z * z;
            }
        }
        #pragma unroll
        for (int i = 0; i < 8; ++i) {
            #pragma unroll
            for (int off = 8; off; off >>= 1) {
                rs[i] += __shfl_xor_sync(0xffffffffu, rs[i], off);
                rq[i] += __shfl_xor_sync(0xffffffffu, rq[i], off);
            }
        }
        float lw[8], lb[8];
        #pragma unroll
        for (int j = 0; j < 8; ++j) {
            lw[j] = lnW[layer * HID + n0 + j];
            lb[j] = lnB[layer * HID + n0 + j];
        }
        if (layer < 2) {
            #pragma unroll
            for (int i = 0; i < 8; ++i) {
                float m   = rs[i] * (1.f / MAXL);
                float inv = rsqrtf(rq[i] * (1.f / MAXL) - m * m + EPS);
                #pragma unroll
                for (int j = 0; j < 8; ++j)
                    dst[(m0 + i) * XS + PAD + n0 + j] = (C[i][j] - m) * inv * lw[j] + lb[j];
            }
            float* t = src; src = dst; dst = t;
            __syncthreads();
        } else {
            float ms[8];
            #pragma unroll
            for (int i = 0; i < 8; ++i) {
                float m   = rs[i] * (1.f / MAXL);
                float inv = rsqrtf(rq[i] * (1.f / MAXL) - m * m + EPS);
                ms[i] = 0.f;
                #pragma unroll
                for (int j = 0; j < 8; ++j) {
                    float o = (C[i][j] - m) * inv * lw[j] + lb[j];
                    if (n0 + j < len) ms[i] += o;
                }
            }
            #pragma unroll
            for (int i = 0; i < 8; ++i) {
                #pragma unroll
                for (int off = 8; off; off >>= 1)
                    ms[i] += __shfl_xor_sync(0xffffffffu, ms[i], off);
            }
            if (tx == 0) {
                #pragma unroll
                for (int i = 0; i < 8; ++i) svec[m0 + i] = ms[i];
            }
        }
    }
    __syncthreads();
    if (tid < HID) {
        float acc = 0.f;
        #pragma unroll 8
        for (int cc = 0; cc < HID; ++cc)
            acc += svec[cc] * outW[cc * HID + tid];
        float cnt   = (float)len;
        float denom = fmaxf(cnt, 1.f);
        g_pooled[n * HID + tid] = (acc + cnt * outB[tid]) / denom;
    }
#endif
}

// ------------------------------------------------------------------
// Classifier head
// ------------------------------------------------------------------
__global__ __launch_bounds__(64) void k_cls(
    const float* __restrict__ W1, const float* __restrict__ b1,
    const float* __restrict__ W2, const float* __restrict__ b2,
    float* __restrict__ out)
{
    __shared__ float p[HID];
    __shared__ float g[64];
    int n = blockIdx.x;
    int j = threadIdx.x;
    p[j]      = g_pooled[n * HID + j];
    p[j + 64] = g_pooled[n * HID + j + 64];
    __syncthreads();
    float acc = b1[j];
    #pragma unroll 8
    for (int cc = 0; cc < HID; ++cc)
        acc += p[cc] * W1[cc * 64 + j];
    g[j] = gelu_exact(acc);
    __syncthreads();
    float acc2 = b2[j];
    #pragma unroll 8
    for (int t = 0; t < 64; ++t)
        acc2 += g[t] * W2[t * 64 + j];
    out[n * NCLS + j] = acc2;
}

// ------------------------------------------------------------------
extern "C" void kernel_launch(void* const* d_in, const int* in_sizes, int n_in,
                              void* d_out, int out_size)
{
    (void)in_sizes; (void)n_in; (void)out_size;
    const float* node_feat  = (const float*)d_in[0];
    const int*   nidx       = (const int*)  d_in[1];
    const int*   nlen       = (const int*)  d_in[2];
    const float* local_W    = (const float*)d_in[3];
    const float* local_b    = (const float*)d_in[4];
    const float* local_ln_w = (const float*)d_in[5];
    const float* local_ln_b = (const float*)d_in[6];
    const float* ssm_in_W   = (const float*)d_in[7];
    const float* ssm_in_b   = (const float*)d_in[8];
    const float* conv_w     = (const float*)d_in[9];
    const float* conv_b     = (const float*)d_in[10];
    const float* ln_w       = (const float*)d_in[11];
    const float* ln_b       = (const float*)d_in[12];
    const float* out_W      = (const float*)d_in[13];
    const float* out_b      = (const float*)d_in[14];
    const float* cls_W1     = (const float*)d_in[15];
    const float* cls_b1     = (const float*)d_in[16];
    const float* cls_W2     = (const float*)d_in[17];
    const float* cls_b2     = (const float*)d_in[18];
    float* out = (float*)d_out;

    cudaFuncSetAttribute(k_main, cudaFuncAttributeMaxDynamicSharedMemorySize, SMEM_TOTAL);

    k_prep<<<(10 * HID * HID + 255) / 256, 256>>>(ssm_in_W, conv_w);
    k_local8<<<N_NODES / 8, 128>>>(node_feat, local_W, local_b, local_ln_w, local_ln_b);
    k_main<<<N_NODES, 288, SMEM_TOTAL>>>(nidx, nlen, ssm_in_b, conv_b, ln_w, ln_b, out_W, out_b);
    k_cls<<<N_NODES, 64>>>(cls_W1, cls_b1, cls_W2, cls_b2, out);
}

// round 14
// speedup vs baseline: 2.0007x; 1.1061x over previous
#include <cuda_runtime.h>
#include <cstdint>

#if defined(__CUDA_ARCH_FEAT_SM103_ALL) || \
    (defined(__CUDA_ARCH_SPECIFIC__) && (__CUDA_ARCH_SPECIFIC__ == 1030)) || \
    (defined(__CUDA_ARCH_FAMILY_SPECIFIC__) && (__CUDA_ARCH_FAMILY_SPECIFIC__ == 1030))
#define TC_PATH 1
#else
#define TC_PATH 0
#endif

#define N_NODES 16384
#define IN_DIM 256
#define HID 128
#define MAXL 128
#define NCLS 64
#define EPS 1e-5f
#define D0 8            // center window (reads D0..D0+127, even write bases)
#define SA 144          // layer-0 shift -1 window (write SA+2, read SA+1)
#define SB 276          // layer-0 shift +1 window (write SB+2, read SB+3)
#define PAD 4
#define XS (MAXL + 2*PAD)

// ---------------- device scratch (no allocations allowed) ----------------
__device__ float g_H[N_NODES * HID];
__device__ float g_pooled[N_NODES * HID];
__device__ float g_Wswz[10 * HID * HID];    // swizzled tf32 tiles (tensor path)
__device__ float g_Wplain[10 * HID * HID];  // plain tiles (fallback path)

// idesc kind::tf32: dtype F32(1<<4), atype TF32(2<<7), btype TF32(2<<10), N=128(16<<17), M=128(8<<24)
static constexpr uint32_t IDESC =
    (1u << 4) | (2u << 7) | (2u << 10) | (16u << 17) | (8u << 24);
// SW128 K-major smem descriptor: layout=2, version=1, SBO=64 (1024B), LBO=1 (16B)
static constexpr uint64_t DESC_BASE =
    (uint64_t(2) << 61) | (uint64_t(1) << 46) | (uint64_t(64) << 32) | (uint64_t(1) << 16);

__device__ __forceinline__ float gelu_exact(float x) {
    return 0.5f * x * (1.0f + erff(x * 0.7071067811865476f));
}
__device__ __forceinline__ float tf32r(float x) {
    uint32_t u;
    asm("cvt.rna.tf32.f32 %0, %1;" : "=r"(u) : "f"(x));
    return __uint_as_float(u);
}
__device__ __forceinline__ uint32_t smem_u32(const void* p) {
    uint32_t a;
    asm("{ .reg .u64 t; cvta.to.shared.u64 t, %1; cvt.u32.u64 %0, t; }" : "=r"(a) : "l"(p));
    return a;
}
// byte offset of (row, col) in a [128 x 128 fp32] K-major SW128 blocked tile
__device__ __forceinline__ uint32_t swz_off(int row, int col) {
    uint32_t off = ((uint32_t)(row >> 3) + (uint32_t)(col >> 5) * 16u) * 1024u
                 + (uint32_t)(row & 7) * 128u + (uint32_t)(col & 31) * 4u;
    return off ^ ((off >> 3) & 0x70u);
}

// ------------------------------------------------------------------
// Prep: weight tiles in both forms.
// tile 0: A[c][k] = ssm_in_W[k][c]; tiles 1..9: A[co][ci] = conv_w[layer][co][ci][kk]
// ------------------------------------------------------------------
__global__ void k_prep(const float* __restrict__ ssmW, const float* __restrict__ convW) {
    int e = blockIdx.x * blockDim.x + threadIdx.x;
    if (e >= 10 * HID * HID) return;
    int tile = e >> 14;
    int r = (e >> 7) & 127;
    int k = e & 127;
    float v;
    if (tile == 0) {
        v = ssmW[k * HID + r];
    } else {
        int t = tile - 1, layer = t / 3, kk = t % 3;
        v = convW[((layer * HID + r) * HID + k) * 3 + kk];
    }
    g_Wplain[tile * (HID * HID) + k * HID + r] = v;
    *(float*)((char*)(g_Wswz + tile * (HID * HID)) + swz_off(r, k)) = tf32r(v);
}

// ------------------------------------------------------------------
// Local encoder, 8 nodes per block
// ------------------------------------------------------------------
__global__ __launch_bounds__(128) void k_local8(
    const float* __restrict__ feat, const float* __restrict__ W,
    const float* __restrict__ b, const float* __restrict__ lnw,
    const float* __restrict__ lnb)
{
    __shared__ float xs[8 * IN_DIM];
    __shared__ float reds[32], redq[32];
    int base = blockIdx.x * 8;
    int c = threadIdx.x;
    for (int e = c; e < 8 * IN_DIM; e += 128)
        xs[e] = feat[base * IN_DIM + e];
    __syncthreads();

    float acc[8];
    float bb = b[c];
    #pragma unroll
    for (int nb = 0; nb < 8; ++nb) acc[nb] = bb;
    for (int i = 0; i < IN_DIM; ++i) {
        float wv = W[i * HID + c];
        #pragma unroll
        for (int nb = 0; nb < 8; ++nb) acc[nb] += xs[nb * IN_DIM + i] * wv;
    }
    int warp = c >> 5, lane = c & 31;
    float v[8];
    #pragma unroll
    for (int nb = 0; nb < 8; ++nb) {
        v[nb] = gelu_exact(acc[nb]);
        float s = v[nb], q = v[nb] * v[nb];
        #pragma unroll
        for (int off = 16; off; off >>= 1) {
            s += __shfl_xor_sync(0xffffffffu, s, off);
            q += __shfl_xor_sync(0xffffffffu, q, off);
        }
        if (lane == 0) { reds[warp * 8 + nb] = s; redq[warp * 8 + nb] = q; }
    }
    __syncthreads();
    #pragma unroll
    for (int nb = 0; nb < 8; ++nb) {
        float s = reds[nb] + reds[8 + nb] + reds[16 + nb] + reds[24 + nb];
        float q = redq[nb] + redq[8 + nb] + redq[16 + nb] + redq[24 + nb];
        float m = s * (1.f / HID);
        float inv = rsqrtf(q * (1.f / HID) - m * m + EPS);
        g_H[(base + nb) * HID + c] = (v[nb] - m) * inv * lnw[c] + lnb[c];
    }
}

// ================= tensor-path helpers (guarded) =================
#if TC_PATH
#define MBAR_INIT(a, cnt) \
    asm volatile("mbarrier.init.shared.b64 [%0], %1;" :: "r"(a), "r"((uint32_t)(cnt)) : "memory")
#define MBAR_EXPECT(a, bytes) \
    asm volatile("mbarrier.arrive.expect_tx.shared.b64 _, [%0], %1;" :: "r"(a), "r"((uint32_t)(bytes)) : "memory")

__device__ __forceinline__ void mbar_wait(uint32_t mbar, int parity) {
    asm volatile(
        "{\n\t.reg .pred P1;\n\t"
        "WL_%=:\n\t"
        "mbarrier.try_wait.parity.acquire.cta.shared::cta.b64 P1, [%0], %1, 0x989680;\n\t"
        "@P1 bra.uni WD_%=;\n\t"
        "bra.uni WL_%=;\n\t"
        "WD_%=:\n\t}"
        :: "r"(mbar), "r"((uint32_t)parity) : "memory");
}
__device__ __forceinline__ void bulk_g2s(uint32_t dst, const void* src, uint32_t bytes, uint32_t mbar) {
    asm volatile(
        "cp.async.bulk.shared::cluster.global.mbarrier::complete_tx::bytes [%0], [%1], %2, [%3];"
        :: "r"(dst), "l"(src), "r"(bytes), "r"(mbar) : "memory");
}

#define TC_ALLOC(sa, n) \
    asm volatile("tcgen05.alloc.cta_group::1.sync.aligned.shared::cta.b32 [%0], %1;" :: "r"(sa), "r"((uint32_t)(n)) : "memory")
#define TC_RELINQ() \
    asm volatile("tcgen05.relinquish_alloc_permit.cta_group::1.sync.aligned;")
#define TC_DEALLOC(t, n) \
    asm volatile("tcgen05.dealloc.cta_group::1.sync.aligned.b32 %0, %1;" :: "r"(t), "r"((uint32_t)(n)))
#define TC_COMMIT(mb) \
    asm volatile("tcgen05.commit.cta_group::1.mbarrier::arrive::one.shared::cluster.b64 [%0];" :: "r"(mb) : "memory")
#define TC_FENCE_BEFORE() asm volatile("tcgen05.fence::before_thread_sync;" ::: "memory")
#define TC_FENCE_AFTER()  asm volatile("tcgen05.fence::after_thread_sync;" ::: "memory")
#define TC_WAIT_LD() asm volatile("tcgen05.wait::ld.sync.aligned;" ::: "memory")
#define TC_WAIT_ST() asm volatile("tcgen05.wait::st.sync.aligned;" ::: "memory")
#define FENCE_PROXY() asm volatile("fence.proxy.async.shared::cta;" ::: "memory")

#define TCLD32(r, adr) \
    asm volatile( \
        "tcgen05.ld.sync.aligned.32x32b.x32.b32 " \
        "{%0, %1, %2, %3, %4, %5, %6, %7, %8, %9, %10, %11, %12, %13, %14, %15, " \
        " %16, %17, %18, %19, %20, %21, %22, %23, %24, %25, %26, %27, %28, %29, %30, %31}, [%32];" \
        : "=r"((r)[0]),  "=r"((r)[1]),  "=r"((r)[2]),  "=r"((r)[3]), \
          "=r"((r)[4]),  "=r"((r)[5]),  "=r"((r)[6]),  "=r"((r)[7]), \
          "=r"((r)[8]),  "=r"((r)[9]),  "=r"((r)[10]), "=r"((r)[11]), \
          "=r"((r)[12]), "=r"((r)[13]), "=r"((r)[14]), "=r"((r)[15]), \
          "=r"((r)[16]), "=r"((r)[17]), "=r"((r)[18]), "=r"((r)[19]), \
          "=r"((r)[20]), "=r"((r)[21]), "=r"((r)[22]), "=r"((r)[23]), \
          "=r"((r)[24]), "=r"((r)[25]), "=r"((r)[26]), "=r"((r)[27]), \
          "=r"((r)[28]), "=r"((r)[29]), "=r"((r)[30]), "=r"((r)[31]) \
        : "r"(adr))

#define TCST2(adr, r0, r1) \
    asm volatile("tcgen05.st.sync.aligned.32x32b.x2.b32 [%0], {%1, %2};" \
                 :: "r"(adr), "r"(r0), "r"(r1) : "memory")

__device__ __forceinline__ void mma_tf32(uint32_t d, uint64_t a, uint64_t b, uint32_t en) {
    asm volatile(
        "{\n\t.reg .pred p;\n\tsetp.ne.u32 p, %4, 0;\n\t"
        "tcgen05.mma.cta_group::1.kind::tf32 [%0], %1, %2, %3, {%5, %5, %5, %5}, p;\n\t}"
        :: "r"(d), "l"(a), "l"(b), "r"(IDESC), "r"(en), "r"(0u) : "memory");
}
#endif  // TC_PATH

// ================= fallback fp32 microkernel (compiled always; dead on sm_103a) =================
template<int SHIFT>
__device__ __forceinline__ void gemm_tap(float C[8][8], const float* __restrict__ Wt,
                                         const float* __restrict__ B, int m0, int n0)
{
    const float* brow = B + PAD + n0 + SHIFT;
    const float* wrow = Wt + m0;
    #pragma unroll 2
    for (int k = 0; k < HID; ++k) {
        float a[8], bb[8];
        float4 a0 = *(const float4*)(wrow);
        float4 a1 = *(const float4*)(wrow + 4);
        a[0]=a0.x; a[1]=a0.y; a[2]=a0.z; a[3]=a0.w;
        a[4]=a1.x; a[5]=a1.y; a[6]=a1.z; a[7]=a1.w;
        #pragma unroll
        for (int j = 0; j < 8; ++j) bb[j] = brow[j];
        #pragma unroll
        for (int i = 0; i < 8; ++i)
            #pragma unroll
            for (int j = 0; j < 8; ++j)
                C[i][j] += a[i] * bb[j];
        wrow += HID;
        brow += XS;
    }
}

// ------------------------------------------------------------------
// Main kernel (round-4 proven structure; gather vectorized; DBASE fixed to
// consumption order: slot1 = tile2 = CENTER -> D0, slot2 = tile1 = kk0 -> SA+2).
// smem (floats, 1KB-aligned base):
//   Bt@0 (16384) | A0@16384 (16384) | A1@32768 (16384) | Par@49152 (1280)
//   | RedS@50432 | RedQ@50688 | Svec@50944 | misc bytes @204288
// ------------------------------------------------------------------
#define SMF_A0   16384
#define SMF_A1   32768
#define SMF_PAR  49152
#define SMF_REDS 50432
#define SMF_REDQ 50688
#define SMF_SVEC 50944
#define SMB_MISC 204288
#define SMEM_TOTAL 205504

__global__ __launch_bounds__(256, 1) void k_main(
    const int* __restrict__ nidx, const int* __restrict__ nlen,
    const float* __restrict__ ssmB, const float* __restrict__ convB,
    const float* __restrict__ lnW, const float* __restrict__ lnB,
    const float* __restrict__ outW, const float* __restrict__ outB)
{
    extern __shared__ float smf[];
    const int n = blockIdx.x;
    const int tid = threadIdx.x;
    const int len = nlen[n];

#if TC_PATH
    uint32_t raw = smem_u32(smf);
    uint32_t sbase = (raw + 1023u) & ~1023u;
    float* bas = smf + (sbase - raw) / 4;

    float* Bt   = bas;
    float* Par  = bas + SMF_PAR;
    float* RedS = bas + SMF_REDS;
    float* RedQ = bas + SMF_REDQ;
    float* Svec = bas + SMF_SVEC;
    uint32_t Baddr = sbase;
    uint32_t Aaddr[2] = {sbase + SMF_A0 * 4u, sbase + SMF_A1 * 4u};
    uint32_t miscb = sbase + SMB_MISC;        // tmem ptr @+0
    uint32_t mb_tma[2] = {miscb + 8, miscb + 16};
    uint32_t mb_mma[2] = {miscb + 24, miscb + 32};
    uint32_t mb_grp = miscb + 40;

    const int w = tid >> 5, lane = tid & 31;
    const int h = w >> 2;                  // column half
    const int c = (w & 3) * 32 + lane;     // channel (TMEM row) owned
    const uint32_t woff = (uint32_t)(w & 3) << 21;

    if (tid == 0) {
        MBAR_INIT(mb_tma[0], 1); MBAR_INIT(mb_tma[1], 1);
        MBAR_INIT(mb_mma[0], 1); MBAR_INIT(mb_mma[1], 1);
        MBAR_INIT(mb_grp, 1);
    }
    for (int e = tid; e < 128; e += 256) Par[e] = ssmB[e];
    for (int e = tid; e < 384; e += 256) Par[128 + e] = convB[e];
    for (int e = tid; e < 384; e += 256) Par[512 + e] = lnW[e];
    for (int e = tid; e < 384; e += 256) Par[896 + e] = lnB[e];
    if (w == 0) TC_ALLOC(miscb, 512);
    __syncthreads();
    uint32_t tmem;
    asm("ld.shared.b32 %0, [%1];" : "=r"(tmem) : "r"(miscb));
    if (w == 0) TC_RELINQ();

    if (tid == 0) {   // preload tiles TSEQ[0]=0 and TSEQ[1]=2
        MBAR_EXPECT(mb_tma[0], 65536);
        bulk_g2s(Aaddr[0], g_Wswz, 65536, mb_tma[0]);
        MBAR_EXPECT(mb_tma[1], 65536);
        bulk_g2s(Aaddr[1], g_Wswz + 2 * 16384, 65536, mb_tma[1]);
    }

    // ---- VECTORIZED gather: B[l][k] = H[idx[l]][k], float4 granules ----
    // SW128 XOR key = off bits 7-9 -> bits 4-6; constant within a 16B granule,
    // so each float4 lands contiguous & aligned at swz_off(l, 4g).
    {
        const int* idxrow = nidx + n * MAXL;
        const float4* Hv = (const float4*)g_H;
        for (int e = tid; e < MAXL * 32; e += 256) {
            int l = e >> 5, g = e & 31;
            float4 v = make_float4(0.f, 0.f, 0.f, 0.f);
            if (l < len) {
                v = Hv[(size_t)idxrow[l] * 32 + g];
                v.x = tf32r(v.x); v.y = tf32r(v.y);
                v.z = tf32r(v.z); v.w = tf32r(v.w);
            }
            *(float4*)((char*)Bt + swz_off(l, g * 4)) = v;
        }
    }

    // zero margin columns of side windows: SA..SA+1 and SB+130..SB+131 (all 128 rows)
    if (h == 0) {
        uint32_t tb = tmem + woff;
        TCST2(tb + SA, 0u, 0u);
        TCST2(tb + SB + 130, 0u, 0u);
        TC_WAIT_ST();
        TC_FENCE_BEFORE();
    }

    int tma_ph[2] = {0, 0}, mma_ph[2] = {0, 0};
    int cons = 0;
    uint32_t va[32], vb[32];

    for (int stage = 0; stage < 4; ++stage) {
        __syncthreads();   // B tile ready; TMEM stores visible

        if (tid == 0) {
            // Indexed by CONSUMPTION slot t. Tiles stream as TSEQ, so within each
            // conv stage the order is CENTER (kk1), then kk0, then kk2:
            //   slot1 = tile2 (L0 center, s=0)  -> D0,   overwrite
            //   slot2 = tile1 (L0 kk0,  s=-1)   -> SA+2, overwrite (own window)
            //   slot3 = tile3 (L0 kk2,  s=+1)   -> SB+2, overwrite (own window)
            //   slot5 = tile4 (L1 kk0,  s=-2)   -> D0+2, accumulate   etc.
            const int TSEQ[10] = {0, 2, 1, 3, 5, 4, 6, 8, 7, 9};
            const int DBASE[10]= {D0, D0, SA + 2, SB + 2, D0, D0 + 2, D0 - 2, D0, D0 + 4, D0 - 4};
            const int INITT[10]= {1, 1, 1, 1, 1, 0, 0, 1, 0, 0};
            FENCE_PROXY();
            TC_FENCE_AFTER();
            uint64_t bd0 = DESC_BASE | ((uint64_t)((Baddr >> 4) & 0x3FFFu));
            int tA = (stage == 0) ? 0 : 1 + (stage - 1) * 3;
            int tB = (stage == 0) ? 0 : tA + 2;
            for (int t = tA; t <= tB; ++t) {
                int bidx = cons & 1;
                mbar_wait(mb_tma[bidx], tma_ph[bidx]); tma_ph[bidx] ^= 1;
                uint64_t ad = DESC_BASE | ((uint64_t)((Aaddr[bidx] >> 4) & 0x3FFFu));
                uint32_t dadr = tmem + (uint32_t)DBASE[t];
                #pragma unroll
                for (int ks = 0; ks < 16; ++ks) {
                    uint64_t o = (uint64_t)((ks & 3) * 2 + (ks >> 2) * 1024);
                    uint32_t en = (ks == 0 && INITT[t]) ? 0u : 1u;
                    mma_tf32(dadr, ad + o, bd0 + o, en);
                }
                TC_COMMIT(mb_mma[bidx]);
                if (cons + 2 <= 9) {
                    mbar_wait(mb_mma[bidx], mma_ph[bidx]); mma_ph[bidx] ^= 1;
                    MBAR_EXPECT(mb_tma[bidx], 65536);
                    bulk_g2s(Aaddr[bidx], g_Wswz + TSEQ[cons + 2] * 16384, 65536, mb_tma[bidx]);
                }
                cons++;
            }
            TC_COMMIT(mb_grp);
        }
        mbar_wait(mb_grp, stage & 1);
        TC_FENCE_AFTER();

        // ---- epilogue: read D window (plus side windows at stage 1) ----
        TCLD32(va, tmem + woff + (uint32_t)(D0 + 64 * h));
        TCLD32(vb, tmem + woff + (uint32_t)(D0 + 64 * h + 32));
        if (stage == 1) {
            uint32_t ta[32], tb2[32];
            TCLD32(ta,  tmem + woff + (uint32_t)(SA + 1 + 64 * h));
            TCLD32(tb2, tmem + woff + (uint32_t)(SA + 1 + 64 * h + 32));
            TC_WAIT_LD();
            #pragma unroll
            for (int j = 0; j < 32; ++j) {
                va[j] = __float_as_uint(__uint_as_float(va[j]) + __uint_as_float(ta[j]));
                vb[j] = __float_as_uint(__uint_as_float(vb[j]) + __uint_as_float(tb2[j]));
            }
            TCLD32(ta,  tmem + woff + (uint32_t)(SB + 3 + 64 * h));
            TCLD32(tb2, tmem + woff + (uint32_t)(SB + 3 + 64 * h + 32));
            TC_WAIT_LD();
            #pragma unroll
            for (int j = 0; j < 32; ++j) {
                va[j] = __float_as_uint(__uint_as_float(va[j]) + __uint_as_float(ta[j]));
                vb[j] = __float_as_uint(__uint_as_float(vb[j]) + __uint_as_float(tb2[j]));
            }
        } else {
            TC_WAIT_LD();
        }

        if (stage == 0) {
            float bv = Par[c];
            #pragma unroll
            for (int j = 0; j < 32; ++j) {
                int l = 64 * h + j;
                *(float*)((char*)Bt + swz_off(l, c)) = tf32r(__uint_as_float(va[j]) + bv);
            }
            #pragma unroll
            for (int j = 0; j < 32; ++j) {
                int l = 64 * h + 32 + j;
                *(float*)((char*)Bt + swz_off(l, c)) = tf32r(__uint_as_float(vb[j]) + bv);
            }
        } else {
            int layer = stage - 1;
            float bv = Par[128 + layer * 128 + c];
            float s = 0.f, q2 = 0.f;
            #pragma unroll
            for (int j = 0; j < 32; ++j) {
                float z = gelu_exact(__uint_as_float(va[j]) + bv);
                va[j] = __float_as_uint(z); s += z; q2 += z * z;
            }
            #pragma unroll
            for (int j = 0; j < 32; ++j) {
                float z = gelu_exact(__uint_as_float(vb[j]) + bv);
                vb[j] = __float_as_uint(z); s += z; q2 += z * z;
            }
            RedS[h * 128 + c] = s;
            RedQ[h * 128 + c] = q2;
            __syncthreads();
            float st = s + RedS[(h ^ 1) * 128 + c];
            float qt = q2 + RedQ[(h ^ 1) * 128 + c];
            float m   = st * (1.f / 128.f);
            float inv = rsqrtf(qt * (1.f / 128.f) - m * m + EPS);
            const float* lw = Par + 512 + layer * 128;
            const float* lb = Par + 896 + layer * 128;
            if (stage < 3) {
                #pragma unroll
                for (int j = 0; j < 32; ++j) {
                    int l = 64 * h + j;
                    float o = (__uint_as_float(va[j]) - m) * inv * lw[l] + lb[l];
                    *(float*)((char*)Bt + swz_off(l, c)) = tf32r(o);
                }
                #pragma unroll
                for (int j = 0; j < 32; ++j) {
                    int l = 64 * h + 32 + j;
                    float o = (__uint_as_float(vb[j]) - m) * inv * lw[l] + lb[l];
                    *(float*)((char*)Bt + swz_off(l, c)) = tf32r(o);
                }
            } else {
                float ms = 0.f;
                #pragma unroll
                for (int j = 0; j < 32; ++j) {
                    int l = 64 * h + j;
                    float o = (__uint_as_float(va[j]) - m) * inv * lw[l] + lb[l];
                    if (l < len) ms += o;
                }
                #pragma unroll
                for (int j = 0; j < 32; ++j) {
                    int l = 64 * h + 32 + j;
                    float o = (__uint_as_float(vb[j]) - m) * inv * lw[l] + lb[l];
                    if (l < len) ms += o;
                }
                __syncthreads();
                RedS[h * 128 + c] = ms;
                __syncthreads();
                if (h == 0) Svec[c] = RedS[c] + RedS[128 + c];
                __syncthreads();
                if (tid < 128) {
                    float acc = 0.f;
                    #pragma unroll 8
                    for (int cc = 0; cc < 128; ++cc)
                        acc += Svec[cc] * outW[cc * 128 + tid];
                    float cnt = (float)len, denom = fmaxf(cnt, 1.f);
                    g_pooled[n * 128 + tid] = (acc + cnt * outB[tid]) / denom;
                }
            }
        }
    }
    __syncthreads();
    if (w == 0) TC_DEALLOC(tmem, 512);

#else  // ===================== fp32 fallback body (dead on sm_103a device) =====================
    float* Xa   = smf;
    float* Xb   = smf + HID * XS;
    float* Wt   = smf + 2 * HID * XS;
    float* svec = Wt + HID * HID;

    const int tx = tid & 15, ty = tid >> 4;
    const int m0 = ty * 8, n0 = tx * 8;

    for (int e = tid; e < HID * 8; e += 256) {
        int r = e >> 3, p = e & 7;
        int col = (p < PAD) ? p : (XS - 8 + p);
        Xa[r * XS + col] = 0.f;
        Xb[r * XS + col] = 0.f;
    }
    const int* idxrow = nidx + n * MAXL;
    for (int e = tid; e < MAXL * HID; e += 256) {
        int l = e >> 7, k = e & (HID - 1);
        float v = 0.f;
        if (l < len) v = g_H[idxrow[l] * HID + k];
        Xa[k * XS + PAD + l] = v;
    }
    for (int e = tid; e < HID * HID; e += 256) Wt[e] = g_Wplain[e];
    __syncthreads();

    float C[8][8];
    #pragma unroll
    for (int i = 0; i < 8; ++i)
        #pragma unroll
        for (int j = 0; j < 8; ++j) C[i][j] = 0.f;
    gemm_tap<0>(C, Wt, Xa, m0, n0);
    #pragma unroll
    for (int i = 0; i < 8; ++i) {
        float bv = ssmB[m0 + i];
        #pragma unroll
        for (int j = 0; j < 8; ++j)
            Xb[(m0 + i) * XS + PAD + n0 + j] = C[i][j] + bv;
    }
    __syncthreads();

    float* src = Xb;
    float* dst = Xa;
    for (int layer = 0; layer < 3; ++layer) {
        const int d = 1 << layer;
        #pragma unroll
        for (int i = 0; i < 8; ++i)
            #pragma unroll
            for (int j = 0; j < 8; ++j) C[i][j] = 0.f;
        for (int kk = 0; kk < 3; ++kk) {
            const float* wsrc = g_Wplain + (1 + layer * 3 + kk) * (HID * HID);
            for (int e = tid; e < HID * HID; e += 256) Wt[e] = wsrc[e];
            __syncthreads();
            int shift = (kk - 1) * d;
            switch (shift) {
                case -4: gemm_tap<-4>(C, Wt, src, m0, n0); break;
                case -2: gemm_tap<-2>(C, Wt, src, m0, n0); break;
                case -1: gemm_tap<-1>(C, Wt, src, m0, n0); break;
                case  0: gemm_tap< 0>(C, Wt, src, m0, n0); break;
                case  1: gemm_tap< 1>(C, Wt, src, m0, n0); break;
                case  2: gemm_tap< 2>(C, Wt, src, m0, n0); break;
                default: gemm_tap< 4>(C, Wt, src, m0, n0); break;
            }
            __syncthreads();
        }
        float rs[8], rq[8];
        #pragma unroll
        for (int i = 0; i < 8; ++i) {
            float bv = convB[layer * HID + m0 + i];
            rs[i] = 0.f; rq[i] = 0.f;
            #pragma unroll
            for (int j = 0; j < 8; ++j) {
                float z = gelu_exact(C[i][j] + bv);
                C[i][j] = z; rs[i] += z; rq[i] += z * z;
            }
        }
        #pragma unroll
        for (int i = 0; i < 8; ++i) {
            #pragma unroll
            for (int off = 8; off; off >>= 1) {
                rs[i] += __shfl_xor_sync(0xffffffffu, rs[i], off);
                rq[i] += __shfl_xor_sync(0xffffffffu, rq[i], off);
            }
        }
        float lw[8], lb[8];
        #pragma unroll
        for (int j = 0; j < 8; ++j) {
            lw[j] = lnW[layer * HID + n0 + j];
            lb[j] = lnB[layer * HID + n0 + j];
        }
        if (layer < 2) {
            #pragma unroll
            for (int i = 0; i < 8; ++i) {
                float m   = rs[i] * (1.f / MAXL);
                float inv = rsqrtf(rq[i] * (1.f / MAXL) - m * m + EPS);
                #pragma unroll
                for (int j = 0; j < 8; ++j)
                    dst[(m0 + i) * XS + PAD + n0 + j] = (C[i][j] - m) * inv * lw[j] + lb[j];
            }
            float* t = src; src = dst; dst = t;
            __syncthreads();
        } else {
            float ms[8];
            #pragma unroll
            for (int i = 0; i < 8; ++i) {
                float m   = rs[i] * (1.f / MAXL);
                float inv = rsqrtf(rq[i] * (1.f / MAXL) - m * m + EPS);
                ms[i] = 0.f;
                #pragma unroll
                for (int j = 0; j < 8; ++j) {
                    float o = (C[i][j] - m) * inv * lw[j] + lb[j];
                    if (n0 + j < len) ms[i] += o;
                }
            }
            #pragma unroll
            for (int i = 0; i < 8; ++i) {
                #pragma unroll
                for (int off = 8; off; off >>= 1)
                    ms[i] += __shfl_xor_sync(0xffffffffu, ms[i], off);
            }
            if (tx == 0) {
                #pragma unroll
                for (int i = 0; i < 8; ++i) svec[m0 + i] = ms[i];
            }
        }
    }
    __syncthreads();
    if (tid < HID) {
        float acc = 0.f;
        #pragma unroll 8
        for (int cc = 0; cc < HID; ++cc)
            acc += svec[cc] * outW[cc * HID + tid];
        float cnt   = (float)len;
        float denom = fmaxf(cnt, 1.f);
        g_pooled[n * HID + tid] = (acc + cnt * outB[tid]) / denom;
    }
#endif
}

// ------------------------------------------------------------------
// Classifier head
// ------------------------------------------------------------------
__global__ __launch_bounds__(64) void k_cls(
    const float* __restrict__ W1, const float* __restrict__ b1,
    const float* __restrict__ W2, const float* __restrict__ b2,
    float* __restrict__ out)
{
    __shared__ float p[HID];
    __shared__ float g[64];
    int n = blockIdx.x;
    int j = threadIdx.x;
    p[j]      = g_pooled[n * HID + j];
    p[j + 64] = g_pooled[n * HID + j + 64];
    __syncthreads();
    float acc = b1[j];
    #pragma unroll 8
    for (int cc = 0; cc < HID; ++cc)
        acc += p[cc] * W1[cc * 64 + j];
    g[j] = gelu_exact(acc);
    __syncthreads();
    float acc2 = b2[j];
    #pragma unroll 8
    for (int t = 0; t < 64; ++t)
        acc2 += g[t] * W2[t * 64 + j];
    out[n * NCLS + j] = acc2;
}

// ------------------------------------------------------------------
extern "C" void kernel_launch(void* const* d_in, const int* in_sizes, int n_in,
                              void* d_out, int out_size)
{
    (void)in_sizes; (void)n_in; (void)out_size;
    const float* node_feat  = (const float*)d_in[0];
    const int*   nidx       = (const int*)  d_in[1];
    const int*   nlen       = (const int*)  d_in[2];
    const float* local_W    = (const float*)d_in[3];
    const float* local_b    = (const float*)d_in[4];
    const float* local_ln_w = (const float*)d_in[5];
    const float* local_ln_b = (const float*)d_in[6];
    const float* ssm_in_W   = (const float*)d_in[7];
    const float* ssm_in_b   = (const float*)d_in[8];
    const float* conv_w     = (const float*)d_in[9];
    const float* conv_b     = (const float*)d_in[10];
    const float* ln_w       = (const float*)d_in[11];
    const float* ln_b       = (const float*)d_in[12];
    const float* out_W      = (const float*)d_in[13];
    const float* out_b      = (const float*)d_in[14];
    const float* cls_W1     = (const float*)d_in[15];
    const float* cls_b1     = (const float*)d_in[16];
    const float* cls_W2     = (const float*)d_in[17];
    const float* cls_b2     = (const float*)d_in[18];
    float* out = (float*)d_out;

    cudaFuncSetAttribute(k_main, cudaFuncAttributeMaxDynamicSharedMemorySize, SMEM_TOTAL);

    k_prep<<<(10 * HID * HID + 255) / 256, 256>>>(ssm_in_W, conv_w);
    k_local8<<<N_NODES / 8, 128>>>(node_feat, local_W, local_b, local_ln_w, local_ln_b);
    k_main<<<N_NODES, 256, SMEM_TOTAL>>>(nidx, nlen, ssm_in_b, conv_b, ln_w, ln_b, out_W, out_b);
    k_cls<<<N_NODES, 64>>>(cls_W1, cls_b1, cls_W2, cls_b2, out);
}

// round 15
// speedup vs baseline: 2.4513x; 1.2252x over previous
#include <cuda_runtime.h>
#include <cstdint>

#if defined(__CUDA_ARCH_FEAT_SM103_ALL) || \
    (defined(__CUDA_ARCH_SPECIFIC__) && (__CUDA_ARCH_SPECIFIC__ == 1030)) || \
    (defined(__CUDA_ARCH_FAMILY_SPECIFIC__) && (__CUDA_ARCH_FAMILY_SPECIFIC__ == 1030))
#define TC_PATH 1
#else
#define TC_PATH 0
#endif

#define N_NODES 16384
#define IN_DIM 256
#define HID 128
#define MAXL 128
#define NCLS 64
#define EPS 1e-5f
#define D0 8            // center window (reads D0..D0+127, even write bases)
#define SA 144          // layer-0 shift -1 window (write SA+2, read SA+1)
#define SB 276          // layer-0 shift +1 window (write SB+2, read SB+3)
#define PAD 4
#define XS (MAXL + 2*PAD)
#define NPER 8          // nodes per persistent CTA

// ---------------- device scratch (no allocations allowed) ----------------
__device__ float g_H[N_NODES * HID];
__device__ float g_pooled[N_NODES * HID];
__device__ float g_Wswz[10 * HID * HID];    // swizzled tf32 tiles (tensor path)
__device__ float g_Wplain[10 * HID * HID];  // plain tiles (fallback path)

// idesc kind::tf32: dtype F32(1<<4), atype TF32(2<<7), btype TF32(2<<10), N=128(16<<17), M=128(8<<24)
static constexpr uint32_t IDESC =
    (1u << 4) | (2u << 7) | (2u << 10) | (16u << 17) | (8u << 24);
// SW128 K-major smem descriptor: layout=2, version=1, SBO=64 (1024B), LBO=1 (16B)
static constexpr uint64_t DESC_BASE =
    (uint64_t(2) << 61) | (uint64_t(1) << 46) | (uint64_t(64) << 32) | (uint64_t(1) << 16);

__device__ __forceinline__ float gelu_exact(float x) {
    return 0.5f * x * (1.0f + erff(x * 0.7071067811865476f));
}
__device__ __forceinline__ float tf32r(float x) {
    uint32_t u;
    asm("cvt.rna.tf32.f32 %0, %1;" : "=r"(u) : "f"(x));
    return __uint_as_float(u);
}
__device__ __forceinline__ uint32_t smem_u32(const void* p) {
    uint32_t a;
    asm("{ .reg .u64 t; cvta.to.shared.u64 t, %1; cvt.u32.u64 %0, t; }" : "=r"(a) : "l"(p));
    return a;
}
// byte offset of (row, col) in a [128 x 128 fp32] K-major SW128 blocked tile
__device__ __forceinline__ uint32_t swz_off(int row, int col) {
    uint32_t off = ((uint32_t)(row >> 3) + (uint32_t)(col >> 5) * 16u) * 1024u
                 + (uint32_t)(row & 7) * 128u + (uint32_t)(col & 31) * 4u;
    return off ^ ((off >> 3) & 0x70u);
}

// ------------------------------------------------------------------
// Prep: weight tiles in both forms.
// tile 0: A[c][k] = ssm_in_W[k][c]; tiles 1..9: A[co][ci] = conv_w[layer][co][ci][kk]
// ------------------------------------------------------------------
__global__ void k_prep(const float* __restrict__ ssmW, const float* __restrict__ convW) {
    int e = blockIdx.x * blockDim.x + threadIdx.x;
    if (e >= 10 * HID * HID) return;
    int tile = e >> 14;
    int r = (e >> 7) & 127;
    int k = e & 127;
    float v;
    if (tile == 0) {
        v = ssmW[k * HID + r];
    } else {
        int t = tile - 1, layer = t / 3, kk = t % 3;
        v = convW[((layer * HID + r) * HID + k) * 3 + kk];
    }
    g_Wplain[tile * (HID * HID) + k * HID + r] = v;
    *(float*)((char*)(g_Wswz + tile * (HID * HID)) + swz_off(r, k)) = tf32r(v);
}

// ------------------------------------------------------------------
// Local encoder, 8 nodes per block
// ------------------------------------------------------------------
__global__ __launch_bounds__(128) void k_local8(
    const float* __restrict__ feat, const float* __restrict__ W,
    const float* __restrict__ b, const float* __restrict__ lnw,
    const float* __restrict__ lnb)
{
    __shared__ float xs[8 * IN_DIM];
    __shared__ float reds[32], redq[32];
    int base = blockIdx.x * 8;
    int c = threadIdx.x;
    for (int e = c; e < 8 * IN_DIM; e += 128)
        xs[e] = feat[base * IN_DIM + e];
    __syncthreads();

    float acc[8];
    float bb = b[c];
    #pragma unroll
    for (int nb = 0; nb < 8; ++nb) acc[nb] = bb;
    for (int i = 0; i < IN_DIM; ++i) {
        float wv = W[i * HID + c];
        #pragma unroll
        for (int nb = 0; nb < 8; ++nb) acc[nb] += xs[nb * IN_DIM + i] * wv;
    }
    int warp = c >> 5, lane = c & 31;
    float v[8];
    #pragma unroll
    for (int nb = 0; nb < 8; ++nb) {
        v[nb] = gelu_exact(acc[nb]);
        float s = v[nb], q = v[nb] * v[nb];
        #pragma unroll
        for (int off = 16; off; off >>= 1) {
            s += __shfl_xor_sync(0xffffffffu, s, off);
            q += __shfl_xor_sync(0xffffffffu, q, off);
        }
        if (lane == 0) { reds[warp * 8 + nb] = s; redq[warp * 8 + nb] = q; }
    }
    __syncthreads();
    #pragma unroll
    for (int nb = 0; nb < 8; ++nb) {
        float s = reds[nb] + reds[8 + nb] + reds[16 + nb] + reds[24 + nb];
        float q = redq[nb] + redq[8 + nb] + redq[16 + nb] + redq[24 + nb];
        float m = s * (1.f / HID);
        float inv = rsqrtf(q * (1.f / HID) - m * m + EPS);
        g_H[(base + nb) * HID + c] = (v[nb] - m) * inv * lnw[c] + lnb[c];
    }
}

// ================= tensor-path helpers (guarded) =================
#if TC_PATH
#define MBAR_INIT(a, cnt) \
    asm volatile("mbarrier.init.shared.b64 [%0], %1;" :: "r"(a), "r"((uint32_t)(cnt)) : "memory")
#define MBAR_EXPECT(a, bytes) \
    asm volatile("mbarrier.arrive.expect_tx.shared.b64 _, [%0], %1;" :: "r"(a), "r"((uint32_t)(bytes)) : "memory")

__device__ __forceinline__ void mbar_wait(uint32_t mbar, int parity) {
    asm volatile(
        "{\n\t.reg .pred P1;\n\t"
        "WL_%=:\n\t"
        "mbarrier.try_wait.parity.acquire.cta.shared::cta.b64 P1, [%0], %1, 0x989680;\n\t"
        "@P1 bra.uni WD_%=;\n\t"
        "bra.uni WL_%=;\n\t"
        "WD_%=:\n\t}"
        :: "r"(mbar), "r"((uint32_t)parity) : "memory");
}
__device__ __forceinline__ void bulk_g2s(uint32_t dst, const void* src, uint32_t bytes, uint32_t mbar) {
    asm volatile(
        "cp.async.bulk.shared::cluster.global.mbarrier::complete_tx::bytes [%0], [%1], %2, [%3];"
        :: "r"(dst), "l"(src), "r"(bytes), "r"(mbar) : "memory");
}

#define TC_ALLOC(sa, n) \
    asm volatile("tcgen05.alloc.cta_group::1.sync.aligned.shared::cta.b32 [%0], %1;" :: "r"(sa), "r"((uint32_t)(n)) : "memory")
#define TC_RELINQ() \
    asm volatile("tcgen05.relinquish_alloc_permit.cta_group::1.sync.aligned;")
#define TC_DEALLOC(t, n) \
    asm volatile("tcgen05.dealloc.cta_group::1.sync.aligned.b32 %0, %1;" :: "r"(t), "r"((uint32_t)(n)))
#define TC_COMMIT(mb) \
    asm volatile("tcgen05.commit.cta_group::1.mbarrier::arrive::one.shared::cluster.b64 [%0];" :: "r"(mb) : "memory")
#define TC_FENCE_BEFORE() asm volatile("tcgen05.fence::before_thread_sync;" ::: "memory")
#define TC_FENCE_AFTER()  asm volatile("tcgen05.fence::after_thread_sync;" ::: "memory")
#define TC_WAIT_LD() asm volatile("tcgen05.wait::ld.sync.aligned;" ::: "memory")
#define TC_WAIT_ST() asm volatile("tcgen05.wait::st.sync.aligned;" ::: "memory")
#define FENCE_PROXY() asm volatile("fence.proxy.async.shared::cta;" ::: "memory")

#define TCLD32(r, adr) \
    asm volatile( \
        "tcgen05.ld.sync.aligned.32x32b.x32.b32 " \
        "{%0, %1, %2, %3, %4, %5, %6, %7, %8, %9, %10, %11, %12, %13, %14, %15, " \
        " %16, %17, %18, %19, %20, %21, %22, %23, %24, %25, %26, %27, %28, %29, %30, %31}, [%32];" \
        : "=r"((r)[0]),  "=r"((r)[1]),  "=r"((r)[2]),  "=r"((r)[3]), \
          "=r"((r)[4]),  "=r"((r)[5]),  "=r"((r)[6]),  "=r"((r)[7]), \
          "=r"((r)[8]),  "=r"((r)[9]),  "=r"((r)[10]), "=r"((r)[11]), \
          "=r"((r)[12]), "=r"((r)[13]), "=r"((r)[14]), "=r"((r)[15]), \
          "=r"((r)[16]), "=r"((r)[17]), "=r"((r)[18]), "=r"((r)[19]), \
          "=r"((r)[20]), "=r"((r)[21]), "=r"((r)[22]), "=r"((r)[23]), \
          "=r"((r)[24]), "=r"((r)[25]), "=r"((r)[26]), "=r"((r)[27]), \
          "=r"((r)[28]), "=r"((r)[29]), "=r"((r)[30]), "=r"((r)[31]) \
        : "r"(adr))

#define TCST2(adr, r0, r1) \
    asm volatile("tcgen05.st.sync.aligned.32x32b.x2.b32 [%0], {%1, %2};" \
                 :: "r"(adr), "r"(r0), "r"(r1) : "memory")

__device__ __forceinline__ void mma_tf32(uint32_t d, uint64_t a, uint64_t b, uint32_t en) {
    asm volatile(
        "{\n\t.reg .pred p;\n\tsetp.ne.u32 p, %4, 0;\n\t"
        "tcgen05.mma.cta_group::1.kind::tf32 [%0], %1, %2, %3, {%5, %5, %5, %5}, p;\n\t}"
        :: "r"(d), "l"(a), "l"(b), "r"(IDESC), "r"(en), "r"(0u) : "memory");
}
#endif  // TC_PATH

// ================= fallback fp32 microkernel (compiled always; dead on sm_103a) =================
template<int SHIFT>
__device__ __forceinline__ void gemm_tap(float C[8][8], const float* __restrict__ Wt,
                                         const float* __restrict__ B, int m0, int n0)
{
    const float* brow = B + PAD + n0 + SHIFT;
    const float* wrow = Wt + m0;
    #pragma unroll 2
    for (int k = 0; k < HID; ++k) {
        float a[8], bb[8];
        float4 a0 = *(const float4*)(wrow);
        float4 a1 = *(const float4*)(wrow + 4);
        a[0]=a0.x; a[1]=a0.y; a[2]=a0.z; a[3]=a0.w;
        a[4]=a1.x; a[5]=a1.y; a[6]=a1.z; a[7]=a1.w;
        #pragma unroll
        for (int j = 0; j < 8; ++j) bb[j] = brow[j];
        #pragma unroll
        for (int i = 0; i < 8; ++i)
            #pragma unroll
            for (int j = 0; j < 8; ++j)
                C[i][j] += a[i] * bb[j];
        wrow += HID;
        brow += XS;
    }
}

// ------------------------------------------------------------------
// Main kernel: persistent (NPER nodes per CTA), 512 threads.
// smem (floats, 1KB-aligned base):
//   Bt@0 (16384) | A0@16384 (16384) | A1@32768 (16384) | Par@49152 (1280)
//   | RedS@50432 (512) | RedQ@50944 (512) | Svec@51456 (128) | misc bytes @206336
// ------------------------------------------------------------------
#define SMF_A0   16384
#define SMF_A1   32768
#define SMF_PAR  49152
#define SMF_REDS 50432
#define SMF_REDQ 50944
#define SMF_SVEC 51456
#define SMB_MISC 206336
#define SMEM_TOTAL 207424

__global__ __launch_bounds__(512, 1) void k_main(
    const int* __restrict__ nidx, const int* __restrict__ nlen,
    const float* __restrict__ ssmB, const float* __restrict__ convB,
    const float* __restrict__ lnW, const float* __restrict__ lnB,
    const float* __restrict__ outW, const float* __restrict__ outB)
{
    extern __shared__ float smf[];
    const int tid = threadIdx.x;

#if TC_PATH
    uint32_t raw = smem_u32(smf);
    uint32_t sbase = (raw + 1023u) & ~1023u;
    float* bas = smf + (sbase - raw) / 4;

    float* Bt   = bas;
    float* Par  = bas + SMF_PAR;
    float* RedS = bas + SMF_REDS;
    float* RedQ = bas + SMF_REDQ;
    float* Svec = bas + SMF_SVEC;
    uint32_t Baddr = sbase;
    uint32_t Aaddr[2] = {sbase + SMF_A0 * 4u, sbase + SMF_A1 * 4u};
    uint32_t miscb = sbase + SMB_MISC;        // tmem ptr @+0
    uint32_t mb_tma[2] = {miscb + 8, miscb + 16};
    uint32_t mb_mma[2] = {miscb + 24, miscb + 32};
    uint32_t mb_grp = miscb + 40;

    const int w = tid >> 5, lane = tid & 31;
    const int h = w >> 2;                  // column quarter (0..3)
    const int c = (w & 3) * 32 + lane;     // channel (TMEM row) owned
    const uint32_t woff = (uint32_t)(w & 3) << 21;

    if (tid == 0) {
        MBAR_INIT(mb_tma[0], 1); MBAR_INIT(mb_tma[1], 1);
        MBAR_INIT(mb_mma[0], 1); MBAR_INIT(mb_mma[1], 1);
        MBAR_INIT(mb_grp, 1);
    }
    for (int e = tid; e < 128; e += 512) Par[e] = ssmB[e];
    for (int e = tid; e < 384; e += 512) Par[128 + e] = convB[e];
    for (int e = tid; e < 384; e += 512) Par[512 + e] = lnW[e];
    for (int e = tid; e < 384; e += 512) Par[896 + e] = lnB[e];
    if (w == 0) TC_ALLOC(miscb, 512);
    __syncthreads();
    uint32_t tmem;
    asm("ld.shared.b32 %0, [%1];" : "=r"(tmem) : "r"(miscb));
    if (w == 0) TC_RELINQ();

    if (tid == 0) {   // preload first two tiles of the continuous ring (TSEQ[0]=0, TSEQ[1]=2)
        MBAR_EXPECT(mb_tma[0], 65536);
        bulk_g2s(Aaddr[0], g_Wswz, 65536, mb_tma[0]);
        MBAR_EXPECT(mb_tma[1], 65536);
        bulk_g2s(Aaddr[1], g_Wswz + 2 * 16384, 65536, mb_tma[1]);
    }

    // zero side-window margins ONCE (MMA never writes them; reused across nodes)
    if (w < 4) {
        uint32_t tb = tmem + woff;
        TCST2(tb + SA, 0u, 0u);
        TCST2(tb + SB + 130, 0u, 0u);
        TC_WAIT_ST();
        TC_FENCE_BEFORE();
    }

    int tma_ph[2] = {0, 0}, mma_ph[2] = {0, 0};
    int gt = 0;    // tid0: global tile counter (0..10*NPER-1)
    int gst = 0;   // all threads: global stage counter
    uint32_t v[32], t2[32];

    for (int ni = 0; ni < NPER; ++ni) {
        const int n = blockIdx.x * NPER + ni;
        const int len = nlen[n];

        // ---- vectorized gather: B[l][k] = H[idx[l]][k] (float4 granules) ----
        {
            const int* idxrow = nidx + n * MAXL;
            const float4* Hv = (const float4*)g_H;
            for (int e = tid; e < MAXL * 32; e += 512) {
                int l = e >> 5, g = e & 31;
                float4 vv = make_float4(0.f, 0.f, 0.f, 0.f);
                if (l < len) {
                    vv = Hv[(size_t)idxrow[l] * 32 + g];
                    vv.x = tf32r(vv.x); vv.y = tf32r(vv.y);
                    vv.z = tf32r(vv.z); vv.w = tf32r(vv.w);
                }
                *(float4*)((char*)Bt + swz_off(l, g * 4)) = vv;
            }
        }

        for (int stage = 0; stage < 4; ++stage) {
            __syncthreads();   // B tile ready (gather or previous epilogue)

            if (tid == 0) {
                // tables indexed by CONSUMPTION slot within node (center, kk0, kk2 order)
                const int TSEQ[10] = {0, 2, 1, 3, 5, 4, 6, 8, 7, 9};
                const int DBASE[10]= {D0, D0, SA + 2, SB + 2, D0, D0 + 2, D0 - 2, D0, D0 + 4, D0 - 4};
                const int INITT[10]= {1, 1, 1, 1, 1, 0, 0, 1, 0, 0};
                FENCE_PROXY();
                TC_FENCE_AFTER();
                uint64_t bd0 = DESC_BASE | ((uint64_t)((Baddr >> 4) & 0x3FFFu));
                int tA = (stage == 0) ? 0 : 1 + (stage - 1) * 3;
                int tB = (stage == 0) ? 0 : tA + 2;
                for (int t = tA; t <= tB; ++t) {
                    int bidx = gt & 1;
                    mbar_wait(mb_tma[bidx], tma_ph[bidx]); tma_ph[bidx] ^= 1;
                    uint64_t ad = DESC_BASE | ((uint64_t)((Aaddr[bidx] >> 4) & 0x3FFFu));
                    uint32_t dadr = tmem + (uint32_t)DBASE[t];
                    #pragma unroll
                    for (int ks = 0; ks < 16; ++ks) {
                        uint64_t o = (uint64_t)((ks & 3) * 2 + (ks >> 2) * 1024);
                        uint32_t en = (ks == 0 && INITT[t]) ? 0u : 1u;
                        mma_tf32(dadr, ad + o, bd0 + o, en);
                    }
                    TC_COMMIT(mb_mma[bidx]);
                    if (gt + 2 < 10 * NPER) {
                        mbar_wait(mb_mma[bidx], mma_ph[bidx]); mma_ph[bidx] ^= 1;
                        MBAR_EXPECT(mb_tma[bidx], 65536);
                        bulk_g2s(Aaddr[bidx], g_Wswz + TSEQ[(gt + 2) % 10] * 16384, 65536,
                                 mb_tma[bidx]);
                    }
                    gt++;
                }
                TC_COMMIT(mb_grp);
            }
            mbar_wait(mb_grp, gst & 1);
            gst++;
            TC_FENCE_AFTER();

            // ---- epilogue: each thread covers 32 columns (quarter h) of channel c ----
            TCLD32(v, tmem + woff + (uint32_t)(D0 + 32 * h));
            TC_WAIT_LD();
            if (stage == 1) {
                TCLD32(t2, tmem + woff + (uint32_t)(SA + 1 + 32 * h));
                TC_WAIT_LD();
                #pragma unroll
                for (int j = 0; j < 32; ++j)
                    v[j] = __float_as_uint(__uint_as_float(v[j]) + __uint_as_float(t2[j]));
                TCLD32(t2, tmem + woff + (uint32_t)(SB + 3 + 32 * h));
                TC_WAIT_LD();
                #pragma unroll
                for (int j = 0; j < 32; ++j)
                    v[j] = __float_as_uint(__uint_as_float(v[j]) + __uint_as_float(t2[j]));
            }

            if (stage == 0) {
                float bv = Par[c];
                #pragma unroll
                for (int j = 0; j < 32; ++j) {
                    int l = 32 * h + j;
                    *(float*)((char*)Bt + swz_off(l, c)) = tf32r(__uint_as_float(v[j]) + bv);
                }
            } else {
                int layer = stage - 1;
                float bv = Par[128 + layer * 128 + c];
                float s = 0.f, q2 = 0.f;
                #pragma unroll
                for (int j = 0; j < 32; ++j) {
                    float z = gelu_exact(__uint_as_float(v[j]) + bv);
                    v[j] = __float_as_uint(z); s += z; q2 += z * z;
                }
                RedS[h * 128 + c] = s;
                RedQ[h * 128 + c] = q2;
                __syncthreads();
                float st = RedS[c] + RedS[128 + c] + RedS[256 + c] + RedS[384 + c];
                float qt = RedQ[c] + RedQ[128 + c] + RedQ[256 + c] + RedQ[384 + c];
                float m   = st * (1.f / 128.f);
                float inv = rsqrtf(qt * (1.f / 128.f) - m * m + EPS);
                const float* lw = Par + 512 + layer * 128;
                const float* lb = Par + 896 + layer * 128;
                if (stage < 3) {
                    #pragma unroll
                    for (int j = 0; j < 32; ++j) {
                        int l = 32 * h + j;
                        float o = (__uint_as_float(v[j]) - m) * inv * lw[l] + lb[l];
                        *(float*)((char*)Bt + swz_off(l, c)) = tf32r(o);
                    }
                } else {
                    // fused masked pooling + 4-way-split out_W matvec
                    float ms = 0.f;
                    #pragma unroll
                    for (int j = 0; j < 32; ++j) {
                        int l = 32 * h + j;
                        float o = (__uint_as_float(v[j]) - m) * inv * lw[l] + lb[l];
                        if (l < len) ms += o;
                    }
                    __syncthreads();       // stats consumed; RedS reusable
                    RedS[h * 128 + c] = ms;
                    __syncthreads();
                    if (h == 0)
                        Svec[c] = RedS[c] + RedS[128 + c] + RedS[256 + c] + RedS[384 + c];
                    __syncthreads();
                    {
                        int q4 = tid >> 7, ch = tid & 127;
                        float acc = 0.f;
                        #pragma unroll 8
                        for (int cc = q4 * 32; cc < q4 * 32 + 32; ++cc)
                            acc += Svec[cc] * outW[cc * 128 + ch];
                        RedQ[q4 * 128 + ch] = acc;
                    }
                    __syncthreads();
                    if (tid < 128) {
                        float tot = RedQ[tid] + RedQ[128 + tid] + RedQ[256 + tid] + RedQ[384 + tid];
                        float cnt = (float)len, denom = fmaxf(cnt, 1.f);
                        g_pooled[n * 128 + tid] = (tot + cnt * outB[tid]) / denom;
                    }
                }
            }
        }
        __syncthreads();   // all TMEM reads of this node done before next node's MMAs
    }
    if (w == 0) TC_DEALLOC(tmem, 512);

#else  // ===================== fp32 fallback body (dead on sm_103a device) =====================
    float* Xa   = smf;
    float* Xb   = smf + HID * XS;
    float* Wt   = smf + 2 * HID * XS;
    float* svec = Wt + HID * HID;

    // threads 256..511 duplicate 0..255 (benign: identical writes; fallback never runs on 103a)
    const int tt = tid & 255;
    const int tx = tt & 15, ty = tt >> 4;
    const int m0 = ty * 8, n0 = tx * 8;

    for (int ni = 0; ni < NPER; ++ni) {
        const int n = blockIdx.x * NPER + ni;
        const int len = nlen[n];
        __syncthreads();
        for (int e = tt; e < HID * 8; e += 256) {
            int r = e >> 3, p = e & 7;
            int col = (p < PAD) ? p : (XS - 8 + p);
            Xa[r * XS + col] = 0.f;
            Xb[r * XS + col] = 0.f;
        }
        const int* idxrow = nidx + n * MAXL;
        for (int e = tt; e < MAXL * HID; e += 256) {
            int l = e >> 7, k = e & (HID - 1);
            float vv = 0.f;
            if (l < len) vv = g_H[idxrow[l] * HID + k];
            Xa[k * XS + PAD + l] = vv;
        }
        for (int e = tt; e < HID * HID; e += 256) Wt[e] = g_Wplain[e];
        __syncthreads();

        float C[8][8];
        #pragma unroll
        for (int i = 0; i < 8; ++i)
            #pragma unroll
            for (int j = 0; j < 8; ++j) C[i][j] = 0.f;
        gemm_tap<0>(C, Wt, Xa, m0, n0);
        #pragma unroll
        for (int i = 0; i < 8; ++i) {
            float bv = ssmB[m0 + i];
            #pragma unroll
            for (int j = 0; j < 8; ++j)
                Xb[(m0 + i) * XS + PAD + n0 + j] = C[i][j] + bv;
        }
        __syncthreads();

        float* src = Xb;
        float* dst = Xa;
        for (int layer = 0; layer < 3; ++layer) {
            const int d = 1 << layer;
            #pragma unroll
            for (int i = 0; i < 8; ++i)
                #pragma unroll
                for (int j = 0; j < 8; ++j) C[i][j] = 0.f;
            for (int kk = 0; kk < 3; ++kk) {
                const float* wsrc = g_Wplain + (1 + layer * 3 + kk) * (HID * HID);
                for (int e = tt; e < HID * HID; e += 256) Wt[e] = wsrc[e];
                __syncthreads();
                int shift = (kk - 1) * d;
                switch (shift) {
                    case -4: gemm_tap<-4>(C, Wt, src, m0, n0); break;
                    case -2: gemm_tap<-2>(C, Wt, src, m0, n0); break;
                    case -1: gemm_tap<-1>(C, Wt, src, m0, n0); break;
                    case  0: gemm_tap< 0>(C, Wt, src, m0, n0); break;
                    case  1: gemm_tap< 1>(C, Wt, src, m0, n0); break;
                    case  2: gemm_tap< 2>(C, Wt, src, m0, n0); break;
                    default: gemm_tap< 4>(C, Wt, src, m0, n0); break;
                }
                __syncthreads();
            }
            float rs[8], rq[8];
            #pragma unroll
            for (int i = 0; i < 8; ++i) {
                float bv = convB[layer * HID + m0 + i];
                rs[i] = 0.f; rq[i] = 0.f;
                #pragma unroll
                for (int j = 0; j < 8; ++j) {
                    float z = gelu_exact(C[i][j] + bv);
                    C[i][j] = z; rs[i] += z; rq[i] += z * z;
                }
            }
            #pragma unroll
            for (int i = 0; i < 8; ++i) {
                #pragma unroll
                for (int off = 8; off; off >>= 1) {
                    rs[i] += __shfl_xor_sync(0xffffffffu, rs[i], off);
                    rq[i] += __shfl_xor_sync(0xffffffffu, rq[i], off);
                }
            }
            float lw[8], lb[8];
            #pragma unroll
            for (int j = 0; j < 8; ++j) {
                lw[j] = lnW[layer * HID + n0 + j];
                lb[j] = lnB[layer * HID + n0 + j];
            }
            if (layer < 2) {
                #pragma unroll
                for (int i = 0; i < 8; ++i) {
                    float m   = rs[i] * (1.f / MAXL);
                    float inv = rsqrtf(rq[i] * (1.f / MAXL) - m * m + EPS);
                    #pragma unroll
                    for (int j = 0; j < 8; ++j)
                        dst[(m0 + i) * XS + PAD + n0 + j] = (C[i][j] - m) * inv * lw[j] + lb[j];
                }
                float* t = src; src = dst; dst = t;
                __syncthreads();
            } else {
                float ms[8];
                #pragma unroll
                for (int i = 0; i < 8; ++i) {
                    float m   = rs[i] * (1.f / MAXL);
                    float inv = rsqrtf(rq[i] * (1.f / MAXL) - m * m + EPS);
                    ms[i] = 0.f;
                    #pragma unroll
                    for (int j = 0; j < 8; ++j) {
                        float o = (C[i][j] - m) * inv * lw[j] + lb[j];
                        if (n0 + j < len) ms[i] += o;
                    }
                }
                #pragma unroll
                for (int i = 0; i < 8; ++i) {
                    #pragma unroll
                    for (int off = 8; off; off >>= 1)
                        ms[i] += __shfl_xor_sync(0xffffffffu, ms[i], off);
                }
                if (tx == 0) {
                    #pragma unroll
                    for (int i = 0; i < 8; ++i) svec[m0 + i] = ms[i];
                }
            }
        }
        __syncthreads();
        if (tt == tid && tid < HID) {
            float acc = 0.f;
            #pragma unroll 8
            for (int cc = 0; cc < HID; ++cc)
                acc += svec[cc] * outW[cc * HID + tid];
            float cnt   = (float)len;
            float denom = fmaxf(cnt, 1.f);
            g_pooled[n * HID + tid] = (acc + cnt * outB[tid]) / denom;
        }
    }
#endif
}

// ------------------------------------------------------------------
// Classifier head
// ------------------------------------------------------------------
__global__ __launch_bounds__(64) void k_cls(
    const float* __restrict__ W1, const float* __restrict__ b1,
    const float* __restrict__ W2, const float* __restrict__ b2,
    float* __restrict__ out)
{
    __shared__ float p[HID];
    __shared__ float g[64];
    int n = blockIdx.x;
    int j = threadIdx.x;
    p[j]      = g_pooled[n * HID + j];
    p[j + 64] = g_pooled[n * HID + j + 64];
    __syncthreads();
    float acc = b1[j];
    #pragma unroll 8
    for (int cc = 0; cc < HID; ++cc)
        acc += p[cc] * W1[cc * 64 + j];
    g[j] = gelu_exact(acc);
    __syncthreads();
    float acc2 = b2[j];
    #pragma unroll 8
    for (int t = 0; t < 64; ++t)
        acc2 += g[t] * W2[t * 64 + j];
    out[n * NCLS + j] = acc2;
}

// ------------------------------------------------------------------
extern "C" void kernel_launch(void* const* d_in, const int* in_sizes, int n_in,
                              void* d_out, int out_size)
{
    (void)in_sizes; (void)n_in; (void)out_size;
    const float* node_feat  = (const float*)d_in[0];
    const int*   nidx       = (const int*)  d_in[1];
    const int*   nlen       = (const int*)  d_in[2];
    const float* local_W    = (const float*)d_in[3];
    const float* local_b    = (const float*)d_in[4];
    const float* local_ln_w = (const float*)d_in[5];
    const float* local_ln_b = (const float*)d_in[6];
    const float* ssm_in_W   = (const float*)d_in[7];
    const float* ssm_in_b   = (const float*)d_in[8];
    const float* conv_w     = (const float*)d_in[9];
    const float* conv_b     = (const float*)d_in[10];
    const float* ln_w       = (const float*)d_in[11];
    const float* ln_b       = (const float*)d_in[12];
    const float* out_W      = (const float*)d_in[13];
    const float* out_b      = (const float*)d_in[14];
    const float* cls_W1     = (const float*)d_in[15];
    const float* cls_b1     = (const float*)d_in[16];
    const float* cls_W2     = (const float*)d_in[17];
    const float* cls_b2     = (const float*)d_in[18];
    float* out = (float*)d_out;

    cudaFuncSetAttribute(k_main, cudaFuncAttributeMaxDynamicSharedMemorySize, SMEM_TOTAL);

    k_prep<<<(10 * HID * HID + 255) / 256, 256>>>(ssm_in_W, conv_w);
    k_local8<<<N_NODES / 8, 128>>>(node_feat, local_W, local_b, local_ln_w, local_ln_b);
    k_main<<<N_NODES / NPER, 512, SMEM_TOTAL>>>(nidx, nlen, ssm_in_b, conv_b, ln_w, ln_b,
                                                out_W, out_b);
    k_cls<<<N_NODES, 64>>>(cls_W1, cls_b1, cls_W2, cls_b2, out);
}

// round 16
// speedup vs baseline: 2.7086x; 1.1050x over previous
#include <cuda_runtime.h>
#include <cstdint>

#if defined(__CUDA_ARCH_FEAT_SM103_ALL) || \
    (defined(__CUDA_ARCH_SPECIFIC__) && (__CUDA_ARCH_SPECIFIC__ == 1030)) || \
    (defined(__CUDA_ARCH_FAMILY_SPECIFIC__) && (__CUDA_ARCH_FAMILY_SPECIFIC__ == 1030))
#define TC_PATH 1
#else
#define TC_PATH 0
#endif

#define N_NODES 16384
#define IN_DIM 256
#define HID 128
#define MAXL 128
#define NCLS 64
#define EPS 1e-5f
#define D0 8            // center window (reads D0..D0+127, even write bases)
#define SA 144          // layer-0 shift -1 window (write SA+2, read SA+1)
#define SB 276          // layer-0 shift +1 window (write SB+2, read SB+3)
#define PAD 4
#define XS (MAXL + 2*PAD)
#define NPER 8          // nodes per persistent CTA
#define NTAP 9          // conv taps only (ssm fused into gather)

// ---------------- device scratch (no allocations allowed) ----------------
__device__ float g_H[N_NODES * HID];
__device__ float g_G[N_NODES * HID];        // G = H @ ssm_in_W + ssm_in_b (fp32)
__device__ float g_pooled[N_NODES * HID];
__device__ float g_Wswz[10 * HID * HID];    // swizzled tf32 tiles (tiles 1..9 used)
__device__ float g_Wplain[10 * HID * HID];  // plain tiles (fallback path)

// idesc kind::tf32: dtype F32(1<<4), atype TF32(2<<7), btype TF32(2<<10), N=128(16<<17), M=128(8<<24)
static constexpr uint32_t IDESC =
    (1u << 4) | (2u << 7) | (2u << 10) | (16u << 17) | (8u << 24);
// SW128 K-major smem descriptor: layout=2, version=1, SBO=64 (1024B), LBO=1 (16B)
static constexpr uint64_t DESC_BASE =
    (uint64_t(2) << 61) | (uint64_t(1) << 46) | (uint64_t(64) << 32) | (uint64_t(1) << 16);

__device__ __forceinline__ float gelu_exact(float x) {
    return 0.5f * x * (1.0f + erff(x * 0.7071067811865476f));
}
__device__ __forceinline__ float tf32r(float x) {
    uint32_t u;
    asm("cvt.rna.tf32.f32 %0, %1;" : "=r"(u) : "f"(x));
    return __uint_as_float(u);
}
__device__ __forceinline__ uint32_t smem_u32(const void* p) {
    uint32_t a;
    asm("{ .reg .u64 t; cvta.to.shared.u64 t, %1; cvt.u32.u64 %0, t; }" : "=r"(a) : "l"(p));
    return a;
}
// byte offset of (row, col) in a [128 x 128 fp32] K-major SW128 blocked tile
__device__ __forceinline__ uint32_t swz_off(int row, int col) {
    uint32_t off = ((uint32_t)(row >> 3) + (uint32_t)(col >> 5) * 16u) * 1024u
                 + (uint32_t)(row & 7) * 128u + (uint32_t)(col & 31) * 4u;
    return off ^ ((off >> 3) & 0x70u);
}

// ------------------------------------------------------------------
// Prep: weight tiles in both forms (tile 0 kept for fallback only).
// ------------------------------------------------------------------
__global__ void k_prep(const float* __restrict__ ssmW, const float* __restrict__ convW) {
    int e = blockIdx.x * blockDim.x + threadIdx.x;
    if (e >= 10 * HID * HID) return;
    int tile = e >> 14;
    int r = (e >> 7) & 127;
    int k = e & 127;
    float v;
    if (tile == 0) {
        v = ssmW[k * HID + r];
    } else {
        int t = tile - 1, layer = t / 3, kk = t % 3;
        v = convW[((layer * HID + r) * HID + k) * 3 + kk];
    }
    g_Wplain[tile * (HID * HID) + k * HID + r] = v;
    *(float*)((char*)(g_Wswz + tile * (HID * HID)) + swz_off(r, k)) = tf32r(v);
}

// ------------------------------------------------------------------
// Local encoder, 8 nodes per block: H = LN(GELU(X @ W + b))
// ------------------------------------------------------------------
__global__ __launch_bounds__(128) void k_local8(
    const float* __restrict__ feat, const float* __restrict__ W,
    const float* __restrict__ b, const float* __restrict__ lnw,
    const float* __restrict__ lnb)
{
    __shared__ float xs[8 * IN_DIM];
    __shared__ float reds[32], redq[32];
    int base = blockIdx.x * 8;
    int c = threadIdx.x;
    for (int e = c; e < 8 * IN_DIM; e += 128)
        xs[e] = feat[base * IN_DIM + e];
    __syncthreads();

    float acc[8];
    float bb = b[c];
    #pragma unroll
    for (int nb = 0; nb < 8; ++nb) acc[nb] = bb;
    for (int i = 0; i < IN_DIM; ++i) {
        float wv = W[i * HID + c];
        #pragma unroll
        for (int nb = 0; nb < 8; ++nb) acc[nb] += xs[nb * IN_DIM + i] * wv;
    }
    int warp = c >> 5, lane = c & 31;
    float v[8];
    #pragma unroll
    for (int nb = 0; nb < 8; ++nb) {
        v[nb] = gelu_exact(acc[nb]);
        float s = v[nb], q = v[nb] * v[nb];
        #pragma unroll
        for (int off = 16; off; off >>= 1) {
            s += __shfl_xor_sync(0xffffffffu, s, off);
            q += __shfl_xor_sync(0xffffffffu, q, off);
        }
        if (lane == 0) { reds[warp * 8 + nb] = s; redq[warp * 8 + nb] = q; }
    }
    __syncthreads();
    #pragma unroll
    for (int nb = 0; nb < 8; ++nb) {
        float s = reds[nb] + reds[8 + nb] + reds[16 + nb] + reds[24 + nb];
        float q = redq[nb] + redq[8 + nb] + redq[16 + nb] + redq[24 + nb];
        float m = s * (1.f / HID);
        float inv = rsqrtf(q * (1.f / HID) - m * m + EPS);
        g_H[(base + nb) * HID + c] = (v[nb] - m) * inv * lnw[c] + lnb[c];
    }
}

// ------------------------------------------------------------------
// G = H @ ssm_in_W + ssm_in_b (fp32), 8 nodes per block
// ------------------------------------------------------------------
__global__ __launch_bounds__(128) void k_ssm(
    const float* __restrict__ W, const float* __restrict__ b)
{
    __shared__ float xs[8 * HID];
    int base = blockIdx.x * 8;
    int c = threadIdx.x;
    for (int e = c; e < 8 * HID; e += 128)
        xs[e] = g_H[base * HID + e];
    __syncthreads();
    float acc[8];
    float bb = b[c];
    #pragma unroll
    for (int nb = 0; nb < 8; ++nb) acc[nb] = bb;
    for (int i = 0; i < HID; ++i) {
        float wv = W[i * HID + c];
        #pragma unroll
        for (int nb = 0; nb < 8; ++nb) acc[nb] += xs[nb * HID + i] * wv;
    }
    #pragma unroll
    for (int nb = 0; nb < 8; ++nb)
        g_G[(base + nb) * HID + c] = acc[nb];
}

// ================= tensor-path helpers (guarded) =================
#if TC_PATH
#define MBAR_INIT(a, cnt) \
    asm volatile("mbarrier.init.shared.b64 [%0], %1;" :: "r"(a), "r"((uint32_t)(cnt)) : "memory")
#define MBAR_EXPECT(a, bytes) \
    asm volatile("mbarrier.arrive.expect_tx.shared.b64 _, [%0], %1;" :: "r"(a), "r"((uint32_t)(bytes)) : "memory")

__device__ __forceinline__ void mbar_wait(uint32_t mbar, int parity) {
    asm volatile(
        "{\n\t.reg .pred P1;\n\t"
        "WL_%=:\n\t"
        "mbarrier.try_wait.parity.acquire.cta.shared::cta.b64 P1, [%0], %1, 0x989680;\n\t"
        "@P1 bra.uni WD_%=;\n\t"
        "bra.uni WL_%=;\n\t"
        "WD_%=:\n\t}"
        :: "r"(mbar), "r"((uint32_t)parity) : "memory");
}
__device__ __forceinline__ void bulk_g2s(uint32_t dst, const void* src, uint32_t bytes, uint32_t mbar) {
    asm volatile(
        "cp.async.bulk.shared::cluster.global.mbarrier::complete_tx::bytes [%0], [%1], %2, [%3];"
        :: "r"(dst), "l"(src), "r"(bytes), "r"(mbar) : "memory");
}

#define TC_ALLOC(sa, n) \
    asm volatile("tcgen05.alloc.cta_group::1.sync.aligned.shared::cta.b32 [%0], %1;" :: "r"(sa), "r"((uint32_t)(n)) : "memory")
#define TC_RELINQ() \
    asm volatile("tcgen05.relinquish_alloc_permit.cta_group::1.sync.aligned;")
#define TC_DEALLOC(t, n) \
    asm volatile("tcgen05.dealloc.cta_group::1.sync.aligned.b32 %0, %1;" :: "r"(t), "r"((uint32_t)(n)))
#define TC_COMMIT(mb) \
    asm volatile("tcgen05.commit.cta_group::1.mbarrier::arrive::one.shared::cluster.b64 [%0];" :: "r"(mb) : "memory")
#define TC_FENCE_BEFORE() asm volatile("tcgen05.fence::before_thread_sync;" ::: "memory")
#define TC_FENCE_AFTER()  asm volatile("tcgen05.fence::after_thread_sync;" ::: "memory")
#define TC_WAIT_LD() asm volatile("tcgen05.wait::ld.sync.aligned;" ::: "memory")
#define TC_WAIT_ST() asm volatile("tcgen05.wait::st.sync.aligned;" ::: "memory")
#define FENCE_PROXY() asm volatile("fence.proxy.async.shared::cta;" ::: "memory")

#define TCLD32(r, adr) \
    asm volatile( \
        "tcgen05.ld.sync.aligned.32x32b.x32.b32 " \
        "{%0, %1, %2, %3, %4, %5, %6, %7, %8, %9, %10, %11, %12, %13, %14, %15, " \
        " %16, %17, %18, %19, %20, %21, %22, %23, %24, %25, %26, %27, %28, %29, %30, %31}, [%32];" \
        : "=r"((r)[0]),  "=r"((r)[1]),  "=r"((r)[2]),  "=r"((r)[3]), \
          "=r"((r)[4]),  "=r"((r)[5]),  "=r"((r)[6]),  "=r"((r)[7]), \
          "=r"((r)[8]),  "=r"((r)[9]),  "=r"((r)[10]), "=r"((r)[11]), \
          "=r"((r)[12]), "=r"((r)[13]), "=r"((r)[14]), "=r"((r)[15]), \
          "=r"((r)[16]), "=r"((r)[17]), "=r"((r)[18]), "=r"((r)[19]), \
          "=r"((r)[20]), "=r"((r)[21]), "=r"((r)[22]), "=r"((r)[23]), \
          "=r"((r)[24]), "=r"((r)[25]), "=r"((r)[26]), "=r"((r)[27]), \
          "=r"((r)[28]), "=r"((r)[29]), "=r"((r)[30]), "=r"((r)[31]) \
        : "r"(adr))

#define TCST2(adr, r0, r1) \
    asm volatile("tcgen05.st.sync.aligned.32x32b.x2.b32 [%0], {%1, %2};" \
                 :: "r"(adr), "r"(r0), "r"(r1) : "memory")

__device__ __forceinline__ void mma_tf32(uint32_t d, uint64_t a, uint64_t b, uint32_t en) {
    asm volatile(
        "{\n\t.reg .pred p;\n\tsetp.ne.u32 p, %4, 0;\n\t"
        "tcgen05.mma.cta_group::1.kind::tf32 [%0], %1, %2, %3, {%5, %5, %5, %5}, p;\n\t}"
        :: "r"(d), "l"(a), "l"(b), "r"(IDESC), "r"(en), "r"(0u) : "memory");
}
#endif  // TC_PATH

// ================= fallback fp32 microkernel (compiled always; dead on sm_103a) =================
template<int SHIFT>
__device__ __forceinline__ void gemm_tap(float C[8][8], const float* __restrict__ Wt,
                                         const float* __restrict__ B, int m0, int n0)
{
    const float* brow = B + PAD + n0 + SHIFT;
    const float* wrow = Wt + m0;
    #pragma unroll 2
    for (int k = 0; k < HID; ++k) {
        float a[8], bb[8];
        float4 a0 = *(const float4*)(wrow);
        float4 a1 = *(const float4*)(wrow + 4);
        a[0]=a0.x; a[1]=a0.y; a[2]=a0.z; a[3]=a0.w;
        a[4]=a1.x; a[5]=a1.y; a[6]=a1.z; a[7]=a1.w;
        #pragma unroll
        for (int j = 0; j < 8; ++j) bb[j] = brow[j];
        #pragma unroll
        for (int i = 0; i < 8; ++i)
            #pragma unroll
            for (int j = 0; j < 8; ++j)
                C[i][j] += a[i] * bb[j];
        wrow += HID;
        brow += XS;
    }
}

// ------------------------------------------------------------------
// Main kernel: persistent (NPER nodes per CTA), 512 threads, 3 stages/node.
// smem layout identical to round 15.
// ------------------------------------------------------------------
#define SMF_A0   16384
#define SMF_A1   32768
#define SMF_PAR  49152
#define SMF_REDS 50432
#define SMF_REDQ 50944
#define SMF_SVEC 51456
#define SMB_MISC 206336
#define SMEM_TOTAL 207424

__global__ __launch_bounds__(512, 1) void k_main(
    const int* __restrict__ nidx, const int* __restrict__ nlen,
    const float* __restrict__ ssmB, const float* __restrict__ convB,
    const float* __restrict__ lnW, const float* __restrict__ lnB,
    const float* __restrict__ outW, const float* __restrict__ outB)
{
    extern __shared__ float smf[];
    const int tid = threadIdx.x;

#if TC_PATH
    uint32_t raw = smem_u32(smf);
    uint32_t sbase = (raw + 1023u) & ~1023u;
    float* bas = smf + (sbase - raw) / 4;

    float* Bt   = bas;
    float* Par  = bas + SMF_PAR;
    float* RedS = bas + SMF_REDS;
    float* RedQ = bas + SMF_REDQ;
    float* Svec = bas + SMF_SVEC;
    uint32_t Baddr = sbase;
    uint32_t Aaddr[2] = {sbase + SMF_A0 * 4u, sbase + SMF_A1 * 4u};
    uint32_t miscb = sbase + SMB_MISC;        // tmem ptr @+0
    uint32_t mb_tma[2] = {miscb + 8, miscb + 16};
    uint32_t mb_mma[2] = {miscb + 24, miscb + 32};
    uint32_t mb_grp = miscb + 40;

    const int w = tid >> 5, lane = tid & 31;
    const int h = w >> 2;                  // column quarter (0..3)
    const int c = (w & 3) * 32 + lane;     // channel (TMEM row) owned
    const uint32_t woff = (uint32_t)(w & 3) << 21;

    if (tid == 0) {
        MBAR_INIT(mb_tma[0], 1); MBAR_INIT(mb_tma[1], 1);
        MBAR_INIT(mb_mma[0], 1); MBAR_INIT(mb_mma[1], 1);
        MBAR_INIT(mb_grp, 1);
    }
    for (int e = tid; e < 128; e += 512) Par[e] = ssmB[e];
    for (int e = tid; e < 384; e += 512) Par[128 + e] = convB[e];
    for (int e = tid; e < 384; e += 512) Par[512 + e] = lnW[e];
    for (int e = tid; e < 384; e += 512) Par[896 + e] = lnB[e];
    if (w == 0) TC_ALLOC(miscb, 512);
    __syncthreads();
    uint32_t tmem;
    asm("ld.shared.b32 %0, [%1];" : "=r"(tmem) : "r"(miscb));
    if (w == 0) TC_RELINQ();

    if (tid == 0) {   // preload first two ring tiles (TSEQ9[0]=2, TSEQ9[1]=1)
        MBAR_EXPECT(mb_tma[0], 65536);
        bulk_g2s(Aaddr[0], g_Wswz + 2 * 16384, 65536, mb_tma[0]);
        MBAR_EXPECT(mb_tma[1], 65536);
        bulk_g2s(Aaddr[1], g_Wswz + 1 * 16384, 65536, mb_tma[1]);
    }

    // zero side-window margins ONCE (MMA never writes them; reused across nodes)
    if (w < 4) {
        uint32_t tb = tmem + woff;
        TCST2(tb + SA, 0u, 0u);
        TCST2(tb + SB + 130, 0u, 0u);
        TC_WAIT_ST();
        TC_FENCE_BEFORE();
    }
    __syncthreads();   // Par (ssmB) visible before first gather

    int tma_ph[2] = {0, 0}, mma_ph[2] = {0, 0};
    int gt = 0;    // tid0: global tile counter (0..NTAP*NPER-1)
    int gst = 0;   // all threads: global stage counter
    uint32_t v[32], t2[32];

    // ---- gather node 0: B[l][k] = (l<len) ? G[idx[l]][k] : ssmB[k] ----
    {
        const int n0g = blockIdx.x * NPER;
        const int len0 = nlen[n0g];
        const int* idxrow = nidx + n0g * MAXL;
        const float4* Gv = (const float4*)g_G;
        const float4* Bv = (const float4*)Par;
        for (int e = tid; e < MAXL * 32; e += 512) {
            int l = e >> 5, g = e & 31;
            float4 vv;
            if (l < len0) vv = Gv[(size_t)idxrow[l] * 32 + g];
            else          vv = Bv[g];
            vv.x = tf32r(vv.x); vv.y = tf32r(vv.y);
            vv.z = tf32r(vv.z); vv.w = tf32r(vv.w);
            *(float4*)((char*)Bt + swz_off(l, g * 4)) = vv;
        }
    }

    for (int ni = 0; ni < NPER; ++ni) {
        const int n = blockIdx.x * NPER + ni;
        const int len = nlen[n];

        for (int stage = 0; stage < 3; ++stage) {     // stage == conv layer
            __syncthreads();   // B tile ready (gather or previous epilogue)

            if (tid == 0) {
                // consumption order per layer: center, kk0, kk2
                const int TSEQ[NTAP] = {2, 1, 3, 5, 4, 6, 8, 7, 9};
                const int DBASE[NTAP]= {D0, SA + 2, SB + 2, D0, D0 + 2, D0 - 2, D0, D0 + 4, D0 - 4};
                const int INITT[NTAP]= {1, 1, 1, 1, 0, 0, 1, 0, 0};
                FENCE_PROXY();
                TC_FENCE_AFTER();
                uint64_t bd0 = DESC_BASE | ((uint64_t)((Baddr >> 4) & 0x3FFFu));
                int tA = 3 * stage, tB = tA + 2;
                for (int t = tA; t <= tB; ++t) {
                    int bidx = gt & 1;
                    mbar_wait(mb_tma[bidx], tma_ph[bidx]); tma_ph[bidx] ^= 1;
                    uint64_t ad = DESC_BASE | ((uint64_t)((Aaddr[bidx] >> 4) & 0x3FFFu));
                    uint32_t dadr = tmem + (uint32_t)DBASE[t];
                    #pragma unroll
                    for (int ks = 0; ks < 16; ++ks) {
                        uint64_t o = (uint64_t)((ks & 3) * 2 + (ks >> 2) * 1024);
                        uint32_t en = (ks == 0 && INITT[t]) ? 0u : 1u;
                        mma_tf32(dadr, ad + o, bd0 + o, en);
                    }
                    TC_COMMIT(mb_mma[bidx]);
                    if (gt + 2 < NTAP * NPER) {
                        mbar_wait(mb_mma[bidx], mma_ph[bidx]); mma_ph[bidx] ^= 1;
                        MBAR_EXPECT(mb_tma[bidx], 65536);
                        bulk_g2s(Aaddr[bidx], g_Wswz + TSEQ[(gt + 2) % NTAP] * 16384, 65536,
                                 mb_tma[bidx]);
                    }
                    gt++;
                }
                TC_COMMIT(mb_grp);
            }
            mbar_wait(mb_grp, gst & 1);
            gst++;
            TC_FENCE_AFTER();

            // ---- epilogue: each thread covers 32 columns (quarter h) of channel c ----
            TCLD32(v, tmem + woff + (uint32_t)(D0 + 32 * h));
            TC_WAIT_LD();
            if (stage == 0) {   // layer 0: combine side windows
                TCLD32(t2, tmem + woff + (uint32_t)(SA + 1 + 32 * h));
                TC_WAIT_LD();
                #pragma unroll
                for (int j = 0; j < 32; ++j)
                    v[j] = __float_as_uint(__uint_as_float(v[j]) + __uint_as_float(t2[j]));
                TCLD32(t2, tmem + woff + (uint32_t)(SB + 3 + 32 * h));
                TC_WAIT_LD();
                #pragma unroll
                for (int j = 0; j < 32; ++j)
                    v[j] = __float_as_uint(__uint_as_float(v[j]) + __uint_as_float(t2[j]));
            }

            int layer = stage;
            float bv = Par[128 + layer * 128 + c];
            float s = 0.f, q2 = 0.f;
            #pragma unroll
            for (int j = 0; j < 32; ++j) {
                float z = gelu_exact(__uint_as_float(v[j]) + bv);
                v[j] = __float_as_uint(z); s += z; q2 += z * z;
            }
            RedS[h * 128 + c] = s;
            RedQ[h * 128 + c] = q2;
            __syncthreads();
            float st = RedS[c] + RedS[128 + c] + RedS[256 + c] + RedS[384 + c];
            float qt = RedQ[c] + RedQ[128 + c] + RedQ[256 + c] + RedQ[384 + c];
            float m   = st * (1.f / 128.f);
            float inv = rsqrtf(qt * (1.f / 128.f) - m * m + EPS);
            const float* lw = Par + 512 + layer * 128;
            const float* lb = Par + 896 + layer * 128;

            if (stage < 2) {
                #pragma unroll
                for (int j = 0; j < 32; ++j) {
                    int l = 32 * h + j;
                    float o = (__uint_as_float(v[j]) - m) * inv * lw[l] + lb[l];
                    *(float*)((char*)Bt + swz_off(l, c)) = tf32r(o);
                }
            } else {
                // final stage: fused masked pooling + overlapped next-node gather + matvec
                float ms = 0.f;
                #pragma unroll
                for (int j = 0; j < 32; ++j) {
                    int l = 32 * h + j;
                    float o = (__uint_as_float(v[j]) - m) * inv * lw[l] + lb[l];
                    if (l < len) ms += o;
                }
                RedS[h * 128 + c] = ms;     // note: RedS stats already consumed above

                // B tile is dead (all stage-2 MMAs completed at mb_grp) -> prefetch next gather
                if (ni + 1 < NPER) {
                    const int n1 = n + 1;
                    const int len1 = nlen[n1];
                    const int* idxrow = nidx + n1 * MAXL;
                    const float4* Gv = (const float4*)g_G;
                    const float4* Bv = (const float4*)Par;
                    for (int e = tid; e < MAXL * 32; e += 512) {
                        int l = e >> 5, g = e & 31;
                        float4 vv;
                        if (l < len1) vv = Gv[(size_t)idxrow[l] * 32 + g];
                        else          vv = Bv[g];
                        vv.x = tf32r(vv.x); vv.y = tf32r(vv.y);
                        vv.z = tf32r(vv.z); vv.w = tf32r(vv.w);
                        *(float4*)((char*)Bt + swz_off(l, g * 4)) = vv;
                    }
                }
                __syncthreads();
                if (h == 0)
                    Svec[c] = RedS[c] + RedS[128 + c] + RedS[256 + c] + RedS[384 + c];
                __syncthreads();
                {
                    int q4 = tid >> 7, ch = tid & 127;
                    float acc = 0.f;
                    #pragma unroll 8
                    for (int cc = q4 * 32; cc < q4 * 32 + 32; ++cc)
                        acc += Svec[cc] * outW[cc * 128 + ch];
                    RedQ[q4 * 128 + ch] = acc;
                }
                __syncthreads();
                if (tid < 128) {
                    float tot = RedQ[tid] + RedQ[128 + tid] + RedQ[256 + tid] + RedQ[384 + tid];
                    float cnt = (float)len, denom = fmaxf(cnt, 1.f);
                    g_pooled[n * 128 + tid] = (tot + cnt * outB[tid]) / denom;
                }
            }
        }
        __syncthreads();   // node's TMEM reads + gather done before next node's MMAs
    }
    if (w == 0) TC_DEALLOC(tmem, 512);

#else  // ===================== fp32 fallback body (dead on sm_103a device) =====================
    float* Xa   = smf;
    float* Xb   = smf + HID * XS;
    float* Wt   = smf + 2 * HID * XS;
    float* svec = Wt + HID * HID;

    const int tt = tid & 255;
    const int tx = tt & 15, ty = tt >> 4;
    const int m0 = ty * 8, n0 = tx * 8;

    for (int ni = 0; ni < NPER; ++ni) {
        const int n = blockIdx.x * NPER + ni;
        const int len = nlen[n];
        __syncthreads();
        for (int e = tt; e < HID * 8; e += 256) {
            int r = e >> 3, p = e & 7;
            int col = (p < PAD) ? p : (XS - 8 + p);
            Xa[r * XS + col] = 0.f;
            Xb[r * XS + col] = 0.f;
        }
        // X0 directly from G (ssm GEMM fused out): Xb[k][l]
        const int* idxrow = nidx + n * MAXL;
        for (int e = tt; e < MAXL * HID; e += 256) {
            int l = e >> 7, k = e & (HID - 1);
            float vv = (l < len) ? g_G[idxrow[l] * HID + k] : ssmB[k];
            Xb[k * XS + PAD + l] = vv;
        }
        __syncthreads();

        float C[8][8];
        float* src = Xb;
        float* dst = Xa;
        for (int layer = 0; layer < 3; ++layer) {
            const int d = 1 << layer;
            #pragma unroll
            for (int i = 0; i < 8; ++i)
                #pragma unroll
                for (int j = 0; j < 8; ++j) C[i][j] = 0.f;
            for (int kk = 0; kk < 3; ++kk) {
                const float* wsrc = g_Wplain + (1 + layer * 3 + kk) * (HID * HID);
                for (int e = tt; e < HID * HID; e += 256) Wt[e] = wsrc[e];
                __syncthreads();
                int shift = (kk - 1) * d;
                switch (shift) {
                    case -4: gemm_tap<-4>(C, Wt, src, m0, n0); break;
                    case -2: gemm_tap<-2>(C, Wt, src, m0, n0); break;
                    case -1: gemm_tap<-1>(C, Wt, src, m0, n0); break;
                    case  0: gemm_tap< 0>(C, Wt, src, m0, n0); break;
                    case  1: gemm_tap< 1>(C, Wt, src, m0, n0); break;
                    case  2: gemm_tap< 2>(C, Wt, src, m0, n0); break;
                    default: gemm_tap< 4>(C, Wt, src, m0, n0); break;
                }
                __syncthreads();
            }
            float rs[8], rq[8];
            #pragma unroll
            for (int i = 0; i < 8; ++i) {
                float bv = convB[layer * HID + m0 + i];
                rs[i] = 0.f; rq[i] = 0.f;
                #pragma unroll
                for (int j = 0; j < 8; ++j) {
                    float z = gelu_exact(C[i][j] + bv);
                    C[i][j] = z; rs[i] += z; rq[i] += z * z;
                }
            }
            #pragma unroll
            for (int i = 0; i < 8; ++i) {
                #pragma unroll
                for (int off = 8; off; off >>= 1) {
                    rs[i] += __shfl_xor_sync(0xffffffffu, rs[i], off);
                    rq[i] += __shfl_xor_sync(0xffffffffu, rq[i], off);
                }
            }
            float lw[8], lb[8];
            #pragma unroll
            for (int j = 0; j < 8; ++j) {
                lw[j] = lnW[layer * HID + n0 + j];
                lb[j] = lnB[layer * HID + n0 + j];
            }
            if (layer < 2) {
                #pragma unroll
                for (int i = 0; i < 8; ++i) {
                    float m   = rs[i] * (1.f / MAXL);
                    float inv = rsqrtf(rq[i] * (1.f / MAXL) - m * m + EPS);
                    #pragma unroll
                    for (int j = 0; j < 8; ++j)
                        dst[(m0 + i) * XS + PAD + n0 + j] = (C[i][j] - m) * inv * lw[j] + lb[j];
                }
                float* t = src; src = dst; dst = t;
                __syncthreads();
            } else {
                float ms[8];
                #pragma unroll
                for (int i = 0; i < 8; ++i) {
                    float m   = rs[i] * (1.f / MAXL);
                    float inv = rsqrtf(rq[i] * (1.f / MAXL) - m * m + EPS);
                    ms[i] = 0.f;
                    #pragma unroll
                    for (int j = 0; j < 8; ++j) {
                        float o = (C[i][j] - m) * inv * lw[j] + lb[j];
                        if (n0 + j < len) ms[i] += o;
                    }
                }
                #pragma unroll
                for (int i = 0; i < 8; ++i) {
                    #pragma unroll
                    for (int off = 8; off; off >>= 1)
                        ms[i] += __shfl_xor_sync(0xffffffffu, ms[i], off);
                }
                if (tx == 0) {
                    #pragma unroll
                    for (int i = 0; i < 8; ++i) svec[m0 + i] = ms[i];
                }
            }
        }
        __syncthreads();
        if (tt == tid && tid < HID) {
            float acc = 0.f;
            #pragma unroll 8
            for (int cc = 0; cc < HID; ++cc)
                acc += svec[cc] * outW[cc * HID + tid];
            float cnt   = (float)len;
            float denom = fmaxf(cnt, 1.f);
            g_pooled[n * HID + tid] = (acc + cnt * outB[tid]) / denom;
        }
    }
#endif
}

// ------------------------------------------------------------------
// Classifier head
// ------------------------------------------------------------------
__global__ __launch_bounds__(64) void k_cls(
    const float* __restrict__ W1, const float* __restrict__ b1,
    const float* __restrict__ W2, const float* __restrict__ b2,
    float* __restrict__ out)
{
    __shared__ float p[HID];
    __shared__ float g[64];
    int n = blockIdx.x;
    int j = threadIdx.x;
    p[j]      = g_pooled[n * HID + j];
    p[j + 64] = g_pooled[n * HID + j + 64];
    __syncthreads();
    float acc = b1[j];
    #pragma unroll 8
    for (int cc = 0; cc < HID; ++cc)
        acc += p[cc] * W1[cc * 64 + j];
    g[j] = gelu_exact(acc);
    __syncthreads();
    float acc2 = b2[j];
    #pragma unroll 8
    for (int t = 0; t < 64; ++t)
        acc2 += g[t] * W2[t * 64 + j];
    out[n * NCLS + j] = acc2;
}

// ------------------------------------------------------------------
extern "C" void kernel_launch(void* const* d_in, const int* in_sizes, int n_in,
                              void* d_out, int out_size)
{
    (void)in_sizes; (void)n_in; (void)out_size;
    const float* node_feat  = (const float*)d_in[0];
    const int*   nidx       = (const int*)  d_in[1];
    const int*   nlen       = (const int*)  d_in[2];
    const float* local_W    = (const float*)d_in[3];
    const float* local_b    = (const float*)d_in[4];
    const float* local_ln_w = (const float*)d_in[5];
    const float* local_ln_b = (const float*)d_in[6];
    const float* ssm_in_W   = (const float*)d_in[7];
    const float* ssm_in_b   = (const float*)d_in[8];
    const float* conv_w     = (const float*)d_in[9];
    const float* conv_b     = (const float*)d_in[10];
    const float* ln_w       = (const float*)d_in[11];
    const float* ln_b       = (const float*)d_in[12];
    const float* out_W      = (const float*)d_in[13];
    const float* out_b      = (const float*)d_in[14];
    const float* cls_W1     = (const float*)d_in[15];
    const float* cls_b1     = (const float*)d_in[16];
    const float* cls_W2     = (const float*)d_in[17];
    const float* cls_b2     = (const float*)d_in[18];
    float* out = (float*)d_out;

    cudaFuncSetAttribute(k_main, cudaFuncAttributeMaxDynamicSharedMemorySize, SMEM_TOTAL);

    k_prep<<<(10 * HID * HID + 255) / 256, 256>>>(ssm_in_W, conv_w);
    k_local8<<<N_NODES / 8, 128>>>(node_feat, local_W, local_b, local_ln_w, local_ln_b);
    k_ssm<<<N_NODES / 8, 128>>>(ssm_in_W, ssm_in_b);
    k_main<<<N_NODES / NPER, 512, SMEM_TOTAL>>>(nidx, nlen, ssm_in_b, conv_b, ln_w, ln_b,
                                                out_W, out_b);
    k_cls<<<N_NODES, 64>>>(cls_W1, cls_b1, cls_W2, cls_b2, out);
}